// round 5
// baseline (speedup 1.0000x reference)
#include <cuda_runtime.h>
#include <math.h>
#include <stdint.h>

#define BATCH  4
#define HEIGHT 128
#define WIDTH  128
#define NPIX   (HEIGHT*WIDTH)      // 16384
#define M_TOT  (BATCH*NPIX)        // 65536
#define DIM    128
#define HEADS  8
#define DH     64
#define INNER  512
#define SLICE  64

// ---------------- scratch (device globals; no allocations) ----------------
__device__ float g_xr  [(size_t)M_TOT*DIM];    // tf32-rounded input [pix][c]
__device__ float g_wb  [18*INNER*DIM];         // conv weights per tap: [pt][o][ci], tf32
__device__ float g_xmid [(size_t)M_TOT*INNER]; // conv_x  out (tf32-rounded)
__device__ float g_fxmid[(size_t)M_TOT*INNER]; // conv_fx out (tf32-rounded)
__device__ float g_sw   [(size_t)BATCH*HEADS*NPIX*SLICE];  // slice weights (tf32-rounded)
__device__ float g_snorm[BATCH*HEADS*SLICE];
__device__ float g_stok [BATCH*HEADS*SLICE*DH];
__device__ float g_osl  [BATCH*HEADS*SLICE*DH];
__device__ float g_pt   [BATCH*DIM*INNER];     // P^T: [b][o][h*64+g] (tf32-rounded)

// ---------------- helpers ----------------
__device__ __forceinline__ float tf32r(float f) {
    uint32_t u;
    asm("cvt.rna.tf32.f32 %0, %1;" : "=r"(u) : "f"(f));
    return __uint_as_float(u);
}
__device__ __forceinline__ void cpa16(uint32_t dst, const void* src, int sz) {
    asm volatile("cp.async.cg.shared.global [%0], [%1], 16, %2;" :: "r"(dst), "l"(src), "r"(sz));
}
#define CP_COMMIT() asm volatile("cp.async.commit_group;" ::: "memory")
#define CP_WAIT2()  asm volatile("cp.async.wait_group 2;" ::: "memory")
__device__ __forceinline__ uint32_t smem_u32(const void* p) {
    uint32_t a;
    asm("{ .reg .u64 t; cvta.to.shared.u64 t, %1; cvt.u32.u64 %0, t; }" : "=r"(a) : "l"(p));
    return a;
}
__device__ __forceinline__ void mma_tf32_16x8x8(float* c, const uint32_t* a, const uint32_t* b) {
    asm volatile("mma.sync.aligned.m16n8k8.row.col.f32.tf32.tf32.f32 "
        "{%0,%1,%2,%3}, {%4,%5,%6,%7}, {%8,%9}, {%0,%1,%2,%3};"
        : "+f"(c[0]), "+f"(c[1]), "+f"(c[2]), "+f"(c[3])
        : "r"(a[0]), "r"(a[1]), "r"(a[2]), "r"(a[3]), "r"(b[0]), "r"(b[1]));
}

// ---------------- prep ----------------
__global__ void prep_kernel(const float* __restrict__ x,
                            const float* __restrict__ Wx, const float* __restrict__ Wfx) {
    int stride = gridDim.x * blockDim.x;
    int tid = blockIdx.x * blockDim.x + threadIdx.x;
    for (size_t t = tid; t < (size_t)M_TOT*DIM; t += stride)
        g_xr[t] = tf32r(x[t]);
    for (int t = tid; t < 18*INNER*DIM; t += stride) {
        int ci = t & 127;
        int o  = (t >> 7) & 511;
        int pt = t >> 16;
        int conv = pt / 9, p = pt % 9;
        int ky = p / 3, kx = p % 3;
        const float* W = conv ? Wfx : Wx;
        g_wb[t] = tf32r(W[((o*DIM + ci)*3 + ky)*3 + kx]);
    }
    for (int t = tid; t < BATCH*HEADS*SLICE; t += stride)    g_snorm[t] = 0.f;
    for (int t = tid; t < BATCH*HEADS*SLICE*DH; t += stride) g_stok[t]  = 0.f;
}

// ---------------- tf32 mma conv: CTA 128x128, warp 32x64, K-chunk 32 ----------------
#define ALD 36
#define STAGE_FLOATS (128*ALD)
#define CONV_DSMEM (6*STAGE_FLOATS*4)        // 110592 B
#define NCHUNK 36

__device__ __forceinline__ void load_chunk_mm(int j, float* sA, float* sB, int tid,
                                              int b, int y, int o0, const float* wt) {
    int p  = j >> 2;
    int c0 = (j & 3) * 32;
    int ky = p / 3, kx = p % 3;
    int yy = y + ky - 1;
    bool rowok = ((unsigned)yy < (unsigned)HEIGHT);
    int yys = rowok ? yy : 0;
    uint32_t sa = smem_u32(sA), sb = smem_u32(sB);
    #pragma unroll
    for (int r = 0; r < 4; r++) {
        int op = tid + r*256;
        int row = op >> 3, q = op & 7;
        int gx = row + kx - 1;
        bool ok = rowok && ((unsigned)gx < (unsigned)WIDTH);
        const float* src = g_xr + ((size_t)((b*HEIGHT + yys)*WIDTH + (ok ? gx : 0)))*DIM + c0 + q*4;
        cpa16(sa + (row*ALD + q*4)*4, src, ok ? 16 : 0);
    }
    #pragma unroll
    for (int r = 0; r < 4; r++) {
        int op = tid + r*256;
        int row = op >> 3, q = op & 7;
        const float* src = wt + ((size_t)(p*INNER + o0 + row))*DIM + c0 + q*4;
        cpa16(sb + (row*ALD + q*4)*4, src, 16);
    }
}

__global__ __launch_bounds__(256) void conv_mm_kernel(const float* __restrict__ bx,
                                                      const float* __restrict__ bfx) {
    extern __shared__ float smb[];
    float* sA = smb;
    float* sB = smb + 3*STAGE_FLOATS;

    int mt = blockIdx.x;
    int b  = mt >> 7, y = mt & 127;
    int m0 = mt * 128;
    int o0 = blockIdx.y * 128;
    int conv = blockIdx.z;
    const float* wt = g_wb + (size_t)conv*9*INNER*DIM;

    int tid  = threadIdx.x;
    int wid  = tid >> 5, lane = tid & 31;
    int g    = lane >> 2, tig = lane & 3;
    int wm   = wid >> 1, wn = wid & 1;

    float c[2][8][4];
    #pragma unroll
    for (int i = 0; i < 2; i++)
        #pragma unroll
        for (int j = 0; j < 8; j++)
            #pragma unroll
            for (int q = 0; q < 4; q++) c[i][j][q] = 0.f;

    load_chunk_mm(0, sA, sB, tid, b, y, o0, wt); CP_COMMIT();
    load_chunk_mm(1, sA + STAGE_FLOATS, sB + STAGE_FLOATS, tid, b, y, o0, wt); CP_COMMIT();

    for (int it = 0; it < NCHUNK; ++it) {
        int j = it + 2;
        if (j < NCHUNK) {
            int s2 = j % 3;
            load_chunk_mm(j, sA + s2*STAGE_FLOATS, sB + s2*STAGE_FLOATS, tid, b, y, o0, wt);
        }
        CP_COMMIT();
        CP_WAIT2();
        __syncthreads();

        const float* As = sA + (it % 3)*STAGE_FLOATS;
        const float* Bs = sB + (it % 3)*STAGE_FLOATS;
        #pragma unroll
        for (int ks = 0; ks < 4; ks++) {
            int k8 = ks*8;
            uint32_t a[2][4];
            #pragma unroll
            for (int mti = 0; mti < 2; mti++) {
                int r0 = wm*32 + mti*16 + g;
                a[mti][0] = __float_as_uint(As[ r0    *ALD + k8 + tig]);
                a[mti][1] = __float_as_uint(As[(r0+8) *ALD + k8 + tig]);
                a[mti][2] = __float_as_uint(As[ r0    *ALD + k8 + tig + 4]);
                a[mti][3] = __float_as_uint(As[(r0+8) *ALD + k8 + tig + 4]);
            }
            uint32_t bf[8][2];
            #pragma unroll
            for (int nti = 0; nti < 8; nti++) {
                int n = wn*64 + nti*8 + g;
                bf[nti][0] = __float_as_uint(Bs[n*ALD + k8 + tig]);
                bf[nti][1] = __float_as_uint(Bs[n*ALD + k8 + tig + 4]);
            }
            #pragma unroll
            for (int mti = 0; mti < 2; mti++)
                #pragma unroll
                for (int nti = 0; nti < 8; nti++)
                    mma_tf32_16x8x8(c[mti][nti], a[mti], bf[nti]);
        }
        __syncthreads();
    }

    float* outp = conv ? g_fxmid : g_xmid;
    const float* bias = conv ? bfx : bx;
    #pragma unroll
    for (int mti = 0; mti < 2; mti++) {
        int r0 = m0 + wm*32 + mti*16 + g;
        #pragma unroll
        for (int nti = 0; nti < 8; nti++) {
            int oc = o0 + wn*64 + nti*8 + tig*2;
            float b0 = bias[oc], b1 = bias[oc+1];
            float2 v0, v1;
            v0.x = tf32r(c[mti][nti][0] + b0); v0.y = tf32r(c[mti][nti][1] + b1);
            v1.x = tf32r(c[mti][nti][2] + b0); v1.y = tf32r(c[mti][nti][3] + b1);
            *(float2*)&outp[(size_t) r0   *INNER + oc] = v0;
            *(float2*)&outp[(size_t)(r0+8)*INNER + oc] = v1;
        }
    }
}

// ---------------- logits: tf32 mma (128x64, K=64) + softmax ----------------
#define LG_SMEM ((128*68 + 64*68 + 128*68 + 64)*4)
__global__ __launch_bounds__(256) void logits_mm_kernel(const float* __restrict__ Ws,
                                                        const float* __restrict__ bs,
                                                        const float* __restrict__ temp_in) {
    extern __shared__ float smb[];
    float* As = smb;                 // [128][68] x_mid tile [n][c]
    float* Bs = smb + 128*68;        // [64][68]  Ws [g][c]
    float* Ls = smb + 128*68 + 64*68;// [128][68] logits
    float* nrm = Ls + 128*68;

    int bh = blockIdx.y;
    int b  = bh >> 3, h = bh & 7;
    int n0 = blockIdx.x * 128;
    int tid = threadIdx.x;
    int wid = tid >> 5, lane = tid & 31;
    int g = lane >> 2, tig = lane & 3;

    const float* xbase = g_xmid + ((size_t)(b*NPIX + n0))*INNER + h*DH;
    #pragma unroll
    for (int r = 0; r < 8; r++) {
        int op = tid + r*256;
        int row = op >> 4, q = op & 15;
        *(float4*)&As[row*68 + 4*q] = *(const float4*)&xbase[(size_t)row*INNER + 4*q];
    }
    #pragma unroll
    for (int r = 0; r < 4; r++) {
        int op = tid + r*256;
        int row = op >> 4, q = op & 15;
        *(float4*)&Bs[row*68 + 4*q] = *(const float4*)&Ws[row*64 + 4*q];
    }
    if (tid < 64) nrm[tid] = 0.f;
    __syncthreads();

    float c[8][4];
    #pragma unroll
    for (int j = 0; j < 8; j++)
        #pragma unroll
        for (int q = 0; q < 4; q++) c[j][q] = 0.f;

    #pragma unroll
    for (int ks = 0; ks < 8; ks++) {
        int k8 = ks*8;
        uint32_t a[4];
        int r0 = wid*16 + g;
        a[0] = __float_as_uint(As[ r0    *68 + k8 + tig]);
        a[1] = __float_as_uint(As[(r0+8) *68 + k8 + tig]);
        a[2] = __float_as_uint(As[ r0    *68 + k8 + tig + 4]);
        a[3] = __float_as_uint(As[(r0+8) *68 + k8 + tig + 4]);
        #pragma unroll
        for (int nti = 0; nti < 8; nti++) {
            uint32_t bf[2];
            int n = nti*8 + g;
            bf[0] = __float_as_uint(Bs[n*68 + k8 + tig]);
            bf[1] = __float_as_uint(Bs[n*68 + k8 + tig + 4]);
            mma_tf32_16x8x8(c[nti], a, bf);
        }
    }
    float t = temp_in[h];
    t = fminf(fmaxf(t, 0.1f), 5.0f);
    float invt = 1.f / t;
    int r0 = wid*16 + g;
    #pragma unroll
    for (int nti = 0; nti < 8; nti++) {
        int col = nti*8 + tig*2;
        Ls[ r0   *68 + col  ] = (c[nti][0] + bs[col  ]) * invt;
        Ls[ r0   *68 + col+1] = (c[nti][1] + bs[col+1]) * invt;
        Ls[(r0+8)*68 + col  ] = (c[nti][2] + bs[col  ]) * invt;
        Ls[(r0+8)*68 + col+1] = (c[nti][3] + bs[col+1]) * invt;
    }
    __syncthreads();

    float s0 = 0.f, s1 = 0.f;
    for (int r16 = 0; r16 < 16; r16++) {
        int row = wid*16 + r16;
        float v0 = Ls[row*68 + lane], v1 = Ls[row*68 + lane + 32];
        float mx = fmaxf(v0, v1);
        #pragma unroll
        for (int off = 16; off; off >>= 1)
            mx = fmaxf(mx, __shfl_xor_sync(0xffffffffu, mx, off));
        float e0 = __expf(v0 - mx), e1 = __expf(v1 - mx);
        float sm = e0 + e1;
        #pragma unroll
        for (int off = 16; off; off >>= 1)
            sm += __shfl_xor_sync(0xffffffffu, sm, off);
        float inv = 1.f / sm;
        e0 *= inv; e1 *= inv;
        float* swp = g_sw + ((size_t)bh*NPIX + n0 + row)*SLICE;
        swp[lane]      = tf32r(e0);
        swp[lane + 32] = tf32r(e1);
        s0 += e0; s1 += e1;
    }
    atomicAdd(&nrm[lane],      s0);
    atomicAdd(&nrm[lane + 32], s1);
    __syncthreads();
    if (tid < 64) atomicAdd(&g_snorm[bh*SLICE + tid], nrm[tid]);
}

// ---------------- slice_token: tf32 mma, st = SW^T @ FX, 32-way K-split ----------------
__global__ __launch_bounds__(256) void stoken_mm_kernel() {
    __shared__ __align__(16) float Asw[64][68];   // [n][g]
    __shared__ __align__(16) float Bfx[64][68];   // [n][c]
    int bh = blockIdx.y;
    int b  = bh >> 3, h = bh & 7;
    int n0 = blockIdx.x * 512;
    int tid = threadIdx.x;
    int wid = tid >> 5, lane = tid & 31;
    int g = lane >> 2, tig = lane & 3;
    int wm = wid >> 1, wn = wid & 1;

    float c[4][4];
    #pragma unroll
    for (int i = 0; i < 4; i++)
        #pragma unroll
        for (int q = 0; q < 4; q++) c[i][q] = 0.f;

    for (int nn = 0; nn < 512; nn += 64) {
        const float* swb = g_sw    + ((size_t)bh*NPIX + n0 + nn)*SLICE;
        const float* fxb = g_fxmid + ((size_t)(b*NPIX + n0 + nn))*INNER + h*DH;
        #pragma unroll
        for (int r = 0; r < 4; r++) {
            int op = tid + r*256;
            int row = op >> 4, q = op & 15;
            *(float4*)&Asw[row][4*q] = *(const float4*)&swb[(size_t)row*SLICE + 4*q];
            *(float4*)&Bfx[row][4*q] = *(const float4*)&fxb[(size_t)row*INNER + 4*q];
        }
        __syncthreads();
        #pragma unroll
        for (int ks = 0; ks < 8; ks++) {
            int k8 = ks*8;
            uint32_t a[4];
            int r0 = wm*16 + g;                       // slice index
            a[0] = __float_as_uint(Asw[k8 + tig    ][r0]);
            a[1] = __float_as_uint(Asw[k8 + tig    ][r0 + 8]);
            a[2] = __float_as_uint(Asw[k8 + tig + 4][r0]);
            a[3] = __float_as_uint(Asw[k8 + tig + 4][r0 + 8]);
            #pragma unroll
            for (int nti = 0; nti < 4; nti++) {
                uint32_t bf[2];
                int col = wn*32 + nti*8 + g;          // channel
                bf[0] = __float_as_uint(Bfx[k8 + tig    ][col]);
                bf[1] = __float_as_uint(Bfx[k8 + tig + 4][col]);
                mma_tf32_16x8x8(c[nti], a, bf);
            }
        }
        __syncthreads();
    }
    int r0 = wm*16 + g;
    #pragma unroll
    for (int nti = 0; nti < 4; nti++) {
        int col = wn*32 + nti*8 + tig*2;
        float* stp = g_stok + bh*4096;
        atomicAdd(&stp[ r0   *64 + col  ], c[nti][0]);
        atomicAdd(&stp[ r0   *64 + col+1], c[nti][1]);
        atomicAdd(&stp[(r0+8)*64 + col  ], c[nti][2]);
        atomicAdd(&stp[(r0+8)*64 + col+1], c[nti][3]);
    }
}

// ---------------- tiny M x M attention per (b,h) ----------------
#define AT_LD 68
#define ATTN_SMEM (5*64*AT_LD*4)
__global__ __launch_bounds__(256) void attn_kernel(const float* __restrict__ Wq,
                                                   const float* __restrict__ Wk,
                                                   const float* __restrict__ Wv) {
    extern __shared__ float smb[];
    float* tok = smb;
    float* wsm = smb + 1*64*AT_LD;
    float* qs  = smb + 2*64*AT_LD;
    float* ks_ = smb + 3*64*AT_LD;
    float* vs  = smb + 4*64*AT_LD;

    int bh  = blockIdx.x;
    int tid = threadIdx.x;

    for (int e = tid; e < 4096; e += 256) {
        int g = e >> 6, c = e & 63;
        float nm = g_snorm[bh*SLICE + g] + 1e-5f;
        tok[g*AT_LD + c] = g_stok[bh*4096 + e] / nm;
    }
    __syncthreads();

    #pragma unroll
    for (int w = 0; w < 3; w++) {
        const float* W = (w == 0) ? Wq : (w == 1) ? Wk : Wv;
        float* dst     = (w == 0) ? qs : (w == 1) ? ks_ : vs;
        for (int e = tid; e < 4096; e += 256)
            wsm[(e >> 6)*AT_LD + (e & 63)] = W[e];
        __syncthreads();
        for (int e = tid; e < 4096; e += 256) {
            int g = e >> 6, d = e & 63;
            float s = 0.f;
            #pragma unroll 8
            for (int c = 0; c < 64; c++)
                s = fmaf(tok[g*AT_LD + c], wsm[d*AT_LD + c], s);
            dst[g*AT_LD + d] = s;
        }
        __syncthreads();
    }
    for (int e = tid; e < 4096; e += 256) {
        int g = e >> 6, j = e & 63;
        float s = 0.f;
        #pragma unroll 8
        for (int d = 0; d < 64; d++)
            s = fmaf(qs[g*AT_LD + d], ks_[j*AT_LD + d], s);
        tok[g*AT_LD + j] = s * 0.125f;
    }
    __syncthreads();
    int wid = tid >> 5, lane = tid & 31;
    for (int r8 = 0; r8 < 8; r8++) {
        int row = wid*8 + r8;
        float v0 = tok[row*AT_LD + lane], v1 = tok[row*AT_LD + lane + 32];
        float mx = fmaxf(v0, v1);
        #pragma unroll
        for (int off = 16; off; off >>= 1)
            mx = fmaxf(mx, __shfl_xor_sync(0xffffffffu, mx, off));
        float e0 = __expf(v0 - mx), e1 = __expf(v1 - mx);
        float sm = e0 + e1;
        #pragma unroll
        for (int off = 16; off; off >>= 1)
            sm += __shfl_xor_sync(0xffffffffu, sm, off);
        float inv = 1.f / sm;
        tok[row*AT_LD + lane]      = e0 * inv;
        tok[row*AT_LD + lane + 32] = e1 * inv;
    }
    __syncthreads();
    for (int e = tid; e < 4096; e += 256) {
        int g = e >> 6, d = e & 63;
        float s = 0.f;
        #pragma unroll 8
        for (int j = 0; j < 64; j++)
            s = fmaf(tok[g*AT_LD + j], vs[j*AT_LD + d], s);
        g_osl[bh*4096 + e] = s;
    }
}

// ---------------- pproj: P^T[b][o][h*64+g] = sum_c osl[bh][g][c] * Wo[o][h*64+c] ----------------
__global__ __launch_bounds__(256) void pproj_kernel(const float* __restrict__ Wo) {
    __shared__ float sosl[64][65];
    __shared__ float swo [128][65];
    int bh = blockIdx.x;
    int b  = bh >> 3, h = bh & 7;
    int tid = threadIdx.x;

    for (int e = tid; e < 4096; e += 256) {
        int g = e >> 6, c = e & 63;
        sosl[g][c] = g_osl[bh*4096 + e];
    }
    for (int e = tid; e < 8192; e += 256) {
        int o = e >> 6, c = e & 63;
        swo[o][c] = Wo[o*INNER + h*DH + c];
    }
    __syncthreads();
    for (int e = tid; e < 8192; e += 256) {
        int o = e >> 6, g = e & 63;
        float s = 0.f;
        #pragma unroll 8
        for (int c = 0; c < 64; c++)
            s = fmaf(sosl[g][c], swo[o][c], s);
        g_pt[(b*DIM + o)*INNER + h*DH + g] = tf32r(s);
    }
}

// ---------------- out GEMM: out_b = SW_b (16384x512) @ P_b^T (512x128), tf32 mma ----------------
__global__ __launch_bounds__(256) void outgemm_kernel(const float* __restrict__ bo,
                                                      float* __restrict__ out) {
    extern __shared__ float smb[];
    float* sA = smb;
    float* sB = smb + 3*STAGE_FLOATS;

    int n0 = blockIdx.x * 128;
    int b  = blockIdx.y;
    int tid  = threadIdx.x;
    int wid  = tid >> 5, lane = tid & 31;
    int g    = lane >> 2, tig = lane & 3;
    int wm   = wid >> 1, wn = wid & 1;

    float c[2][8][4];
    #pragma unroll
    for (int i = 0; i < 2; i++)
        #pragma unroll
        for (int j = 0; j < 8; j++)
            #pragma unroll
            for (int q = 0; q < 4; q++) c[i][j][q] = 0.f;

    // 16 K-chunks of 32
    auto load_chunk = [&](int kk, float* dA, float* dB) {
        int h  = kk >> 1;
        int g0 = (kk & 1) * 32;
        uint32_t sa = smem_u32(dA), sb = smem_u32(dB);
        #pragma unroll
        for (int r = 0; r < 4; r++) {
            int op = tid + r*256;
            int row = op >> 3, q = op & 7;
            const float* srcA = g_sw + ((size_t)((b*HEADS + h)*NPIX) + n0 + row)*SLICE + g0 + q*4;
            cpa16(sa + (row*ALD + q*4)*4, srcA, 16);
            const float* srcB = g_pt + (size_t)(b*DIM + row)*INNER + kk*32 + q*4;
            cpa16(sb + (row*ALD + q*4)*4, srcB, 16);
        }
    };

    load_chunk(0, sA, sB); CP_COMMIT();
    load_chunk(1, sA + STAGE_FLOATS, sB + STAGE_FLOATS); CP_COMMIT();

    for (int it = 0; it < 16; ++it) {
        int j = it + 2;
        if (j < 16) {
            int s2 = j % 3;
            load_chunk(j, sA + s2*STAGE_FLOATS, sB + s2*STAGE_FLOATS);
        }
        CP_COMMIT();
        CP_WAIT2();
        __syncthreads();

        const float* As = sA + (it % 3)*STAGE_FLOATS;
        const float* Bs = sB + (it % 3)*STAGE_FLOATS;
        #pragma unroll
        for (int ks = 0; ks < 4; ks++) {
            int k8 = ks*8;
            uint32_t a[2][4];
            #pragma unroll
            for (int mti = 0; mti < 2; mti++) {
                int r0 = wm*32 + mti*16 + g;
                a[mti][0] = __float_as_uint(As[ r0    *ALD + k8 + tig]);
                a[mti][1] = __float_as_uint(As[(r0+8) *ALD + k8 + tig]);
                a[mti][2] = __float_as_uint(As[ r0    *ALD + k8 + tig + 4]);
                a[mti][3] = __float_as_uint(As[(r0+8) *ALD + k8 + tig + 4]);
            }
            uint32_t bf[8][2];
            #pragma unroll
            for (int nti = 0; nti < 8; nti++) {
                int n = wn*64 + nti*8 + g;
                bf[nti][0] = __float_as_uint(Bs[n*ALD + k8 + tig]);
                bf[nti][1] = __float_as_uint(Bs[n*ALD + k8 + tig + 4]);
            }
            #pragma unroll
            for (int mti = 0; mti < 2; mti++)
                #pragma unroll
                for (int nti = 0; nti < 8; nti++)
                    mma_tf32_16x8x8(c[mti][nti], a[mti], bf[nti]);
        }
        __syncthreads();
    }

    #pragma unroll
    for (int mti = 0; mti < 2; mti++) {
        int r0 = b*NPIX + n0 + wm*32 + mti*16 + g;
        #pragma unroll
        for (int nti = 0; nti < 8; nti++) {
            int oc = wn*64 + nti*8 + tig*2;
            float b0 = bo[oc], b1 = bo[oc+1];
            float2 v0, v1;
            v0.x = c[mti][nti][0] + b0; v0.y = c[mti][nti][1] + b1;
            v1.x = c[mti][nti][2] + b0; v1.y = c[mti][nti][3] + b1;
            *(float2*)&out[(size_t) r0   *DIM + oc] = v0;
            *(float2*)&out[(size_t)(r0+8)*DIM + oc] = v1;
        }
    }
}

// ---------------- launch ----------------
extern "C" void kernel_launch(void* const* d_in, const int* in_sizes, int n_in,
                              void* d_out, int out_size) {
    const float* x           = (const float*)d_in[0];
    const float* temperature = (const float*)d_in[1];
    const float* Wx          = (const float*)d_in[2];
    const float* bx          = (const float*)d_in[3];
    const float* Wfx         = (const float*)d_in[4];
    const float* bfx         = (const float*)d_in[5];
    const float* Ws          = (const float*)d_in[6];
    const float* bs          = (const float*)d_in[7];
    const float* Wq          = (const float*)d_in[8];
    const float* Wk          = (const float*)d_in[9];
    const float* Wv          = (const float*)d_in[10];
    const float* Wo          = (const float*)d_in[11];
    const float* bo          = (const float*)d_in[12];
    float* out = (float*)d_out;

    cudaFuncSetAttribute(conv_mm_kernel, cudaFuncAttributeMaxDynamicSharedMemorySize, CONV_DSMEM);
    cudaFuncSetAttribute(logits_mm_kernel, cudaFuncAttributeMaxDynamicSharedMemorySize, LG_SMEM);
    cudaFuncSetAttribute(attn_kernel, cudaFuncAttributeMaxDynamicSharedMemorySize, ATTN_SMEM);
    cudaFuncSetAttribute(outgemm_kernel, cudaFuncAttributeMaxDynamicSharedMemorySize, CONV_DSMEM);

    prep_kernel<<<2048, 256>>>(x, Wx, Wfx);
    conv_mm_kernel<<<dim3(M_TOT/128, 4, 2), 256, CONV_DSMEM>>>(bx, bfx);
    logits_mm_kernel<<<dim3(NPIX/128, BATCH*HEADS), 256, LG_SMEM>>>(Ws, bs, temperature);
    stoken_mm_kernel<<<dim3(NPIX/512, BATCH*HEADS), 256>>>();
    attn_kernel<<<BATCH*HEADS, 256, ATTN_SMEM>>>(Wq, Wk, Wv);
    pproj_kernel<<<BATCH*HEADS, 256>>>(Wo);
    outgemm_kernel<<<dim3(NPIX/128, BATCH), 256, CONV_DSMEM>>>(bo, out);
}

// round 6
// speedup vs baseline: 1.2057x; 1.2057x over previous
#include <cuda_runtime.h>
#include <math.h>
#include <stdint.h>

#define BATCH  4
#define HEIGHT 128
#define WIDTH  128
#define NPIX   (HEIGHT*WIDTH)      // 16384
#define M_TOT  (BATCH*NPIX)        // 65536
#define DIM    128
#define HEADS  8
#define DH     64
#define INNER  512
#define SLICE  64

// ---------------- scratch (device globals; no allocations) ----------------
__device__ float g_xr  [(size_t)M_TOT*DIM];    // tf32-rounded input [pix][c]
__device__ float g_wb  [18*INNER*DIM];         // conv weights per tap: [pt][o][ci], tf32
__device__ float g_wst [DH*SLICE];             // Ws^T: [c][g]
__device__ float g_wot [INNER*DIM];            // Wo^T: [i][o]
__device__ float g_xmid [(size_t)M_TOT*INNER]; // conv_x  out (tf32-rounded)
__device__ float g_fxmid[(size_t)M_TOT*INNER]; // conv_fx out (tf32-rounded)
__device__ float g_sw   [(size_t)BATCH*HEADS*NPIX*SLICE];
__device__ float g_snorm[BATCH*HEADS*SLICE];
__device__ float g_stok [BATCH*HEADS*SLICE*DH];
__device__ float g_osl  [BATCH*HEADS*SLICE*DH];

// ---------------- helpers ----------------
__device__ __forceinline__ float tf32r(float f) {
    uint32_t u;
    asm("cvt.rna.tf32.f32 %0, %1;" : "=r"(u) : "f"(f));
    return __uint_as_float(u);
}
__device__ __forceinline__ void cpa16(uint32_t dst, const void* src, int sz) {
    asm volatile("cp.async.cg.shared.global [%0], [%1], 16, %2;" :: "r"(dst), "l"(src), "r"(sz));
}
#define CP_COMMIT() asm volatile("cp.async.commit_group;" ::: "memory")
#define CP_WAIT2()  asm volatile("cp.async.wait_group 2;" ::: "memory")
__device__ __forceinline__ uint32_t smem_u32(const void* p) {
    uint32_t a;
    asm("{ .reg .u64 t; cvta.to.shared.u64 t, %1; cvt.u32.u64 %0, t; }" : "=r"(a) : "l"(p));
    return a;
}
__device__ __forceinline__ void mma_tf32_16x8x8(float* c, const uint32_t* a, const uint32_t* b) {
    asm volatile("mma.sync.aligned.m16n8k8.row.col.f32.tf32.tf32.f32 "
        "{%0,%1,%2,%3}, {%4,%5,%6,%7}, {%8,%9}, {%0,%1,%2,%3};"
        : "+f"(c[0]), "+f"(c[1]), "+f"(c[2]), "+f"(c[3])
        : "r"(a[0]), "r"(a[1]), "r"(a[2]), "r"(a[3]), "r"(b[0]), "r"(b[1]));
}
__device__ __forceinline__ void ldsm_x4(uint32_t* r, uint32_t addr) {
    asm volatile("ldmatrix.sync.aligned.m8n8.x4.shared.b16 {%0,%1,%2,%3}, [%4];"
        : "=r"(r[0]), "=r"(r[1]), "=r"(r[2]), "=r"(r[3]) : "r"(addr));
}

// ---------------- prep: tf32 rounding + weight layouts + zero accumulators ----------------
__global__ void prep_kernel(const float* __restrict__ x,
                            const float* __restrict__ Wx, const float* __restrict__ Wfx,
                            const float* __restrict__ Ws, const float* __restrict__ Wo) {
    int stride = gridDim.x * blockDim.x;
    int tid = blockIdx.x * blockDim.x + threadIdx.x;
    for (size_t t = tid; t < (size_t)M_TOT*DIM; t += stride)
        g_xr[t] = tf32r(x[t]);
    for (int t = tid; t < 18*INNER*DIM; t += stride) {
        int ci = t & 127;
        int o  = (t >> 7) & 511;
        int pt = t >> 16;
        int conv = pt / 9, p = pt % 9;
        int ky = p / 3, kx = p % 3;
        const float* W = conv ? Wfx : Wx;
        g_wb[t] = tf32r(W[((o*DIM + ci)*3 + ky)*3 + kx]);
    }
    for (int t = tid; t < DH*SLICE; t += stride) {
        int g = t >> 6, c = t & 63;
        g_wst[c*SLICE + g] = Ws[g*DH + c];
    }
    for (int t = tid; t < INNER*DIM; t += stride) {
        int o = t >> 9, i = t & 511;
        g_wot[i*DIM + o] = Wo[o*INNER + i];
    }
    for (int t = tid; t < BATCH*HEADS*SLICE; t += stride)    g_snorm[t] = 0.f;
    for (int t = tid; t < BATCH*HEADS*SLICE*DH; t += stride) g_stok[t]  = 0.f;
}

// ---------------- tf32 mma conv: CTA 128x128, warp 32x64, K-chunk 32, ldmatrix ----------------
#define ALD 36
#define STAGE_FLOATS (128*ALD)
#define CONV_DSMEM (6*STAGE_FLOATS*4)        // 110592 B
#define NCHUNK 36

__device__ __forceinline__ void load_chunk_mm(int j, float* sA, float* sB, int tid,
                                              int b, int y, int o0, const float* wt) {
    int p  = j >> 2;
    int c0 = (j & 3) * 32;
    int ky = p / 3, kx = p % 3;
    int yy = y + ky - 1;
    bool rowok = ((unsigned)yy < (unsigned)HEIGHT);
    int yys = rowok ? yy : 0;
    uint32_t sa = smem_u32(sA), sb = smem_u32(sB);
    #pragma unroll
    for (int r = 0; r < 4; r++) {
        int op = tid + r*256;
        int row = op >> 3, q = op & 7;
        int gx = row + kx - 1;
        bool ok = rowok && ((unsigned)gx < (unsigned)WIDTH);
        const float* src = g_xr + ((size_t)((b*HEIGHT + yys)*WIDTH + (ok ? gx : 0)))*DIM + c0 + q*4;
        cpa16(sa + (row*ALD + q*4)*4, src, ok ? 16 : 0);
    }
    #pragma unroll
    for (int r = 0; r < 4; r++) {
        int op = tid + r*256;
        int row = op >> 3, q = op & 7;
        const float* src = wt + ((size_t)(p*INNER + o0 + row))*DIM + c0 + q*4;
        cpa16(sb + (row*ALD + q*4)*4, src, 16);
    }
}

__global__ __launch_bounds__(256) void conv_mm_kernel(const float* __restrict__ bx,
                                                      const float* __restrict__ bfx) {
    extern __shared__ float smb[];
    float* sA = smb;
    float* sB = smb + 3*STAGE_FLOATS;

    int mt = blockIdx.x;
    int b  = mt >> 7, y = mt & 127;
    int m0 = mt * 128;
    int o0 = blockIdx.y * 128;
    int conv = blockIdx.z;
    const float* wt = g_wb + (size_t)conv*9*INNER*DIM;

    int tid  = threadIdx.x;
    int wid  = tid >> 5, lane = tid & 31;
    int g    = lane >> 2, tig = lane & 3;
    int wm   = wid >> 1, wn = wid & 1;

    // ldmatrix lane addressing: row = lane&15, k-offset = (lane>>4)*4
    int lrow = lane & 15;
    int lcol = (lane >> 4) * 4;
    uint32_t aOff = ((wm*32 + lrow)*ALD + lcol) * 4;
    uint32_t bOff = ((wn*64 + lrow)*ALD + lcol) * 4;

    float c[2][8][4];
    #pragma unroll
    for (int i = 0; i < 2; i++)
        #pragma unroll
        for (int j = 0; j < 8; j++)
            #pragma unroll
            for (int q = 0; q < 4; q++) c[i][j][q] = 0.f;

    load_chunk_mm(0, sA, sB, tid, b, y, o0, wt); CP_COMMIT();
    load_chunk_mm(1, sA + STAGE_FLOATS, sB + STAGE_FLOATS, tid, b, y, o0, wt); CP_COMMIT();

    for (int it = 0; it < NCHUNK; ++it) {
        int j = it + 2;
        if (j < NCHUNK) {
            int s2 = j % 3;
            load_chunk_mm(j, sA + s2*STAGE_FLOATS, sB + s2*STAGE_FLOATS, tid, b, y, o0, wt);
        }
        CP_COMMIT();
        CP_WAIT2();
        __syncthreads();

        uint32_t saU = smem_u32(sA + (it % 3)*STAGE_FLOATS) + aOff;
        uint32_t sbU = smem_u32(sB + (it % 3)*STAGE_FLOATS) + bOff;
        #pragma unroll
        for (int ks = 0; ks < 4; ks++) {
            uint32_t k8b = ks*8*4;
            uint32_t a[2][4];
            ldsm_x4(a[0], saU + k8b);
            ldsm_x4(a[1], saU + 16*ALD*4 + k8b);
            uint32_t bf[8][2];
            #pragma unroll
            for (int pr = 0; pr < 4; pr++) {
                uint32_t t4[4];
                ldsm_x4(t4, sbU + pr*16*ALD*4 + k8b);
                bf[2*pr  ][0] = t4[0]; bf[2*pr+1][0] = t4[1];
                bf[2*pr  ][1] = t4[2]; bf[2*pr+1][1] = t4[3];
            }
            #pragma unroll
            for (int mti = 0; mti < 2; mti++)
                #pragma unroll
                for (int nti = 0; nti < 8; nti++)
                    mma_tf32_16x8x8(c[mti][nti], a[mti], bf[nti]);
        }
        __syncthreads();
    }

    float* outp = conv ? g_fxmid : g_xmid;
    const float* bias = conv ? bfx : bx;
    #pragma unroll
    for (int mti = 0; mti < 2; mti++) {
        int r0 = m0 + wm*32 + mti*16 + g;
        #pragma unroll
        for (int nti = 0; nti < 8; nti++) {
            int oc = o0 + wn*64 + nti*8 + tig*2;
            float b0 = bias[oc], b1 = bias[oc+1];
            float2 v0, v1;
            v0.x = tf32r(c[mti][nti][0] + b0); v0.y = tf32r(c[mti][nti][1] + b1);
            v1.x = tf32r(c[mti][nti][2] + b0); v1.y = tf32r(c[mti][nti][3] + b1);
            *(float2*)&outp[(size_t) r0   *INNER + oc] = v0;
            *(float2*)&outp[(size_t)(r0+8)*INNER + oc] = v1;
        }
    }
}

// ---------------- logits GEMM + softmax + partial slice_norm (round-3 proven) ----------------
__global__ __launch_bounds__(256) void logits_kernel(const float* __restrict__ bs,
                                                     const float* __restrict__ temp_in) {
    __shared__ __align__(16) float xs[64][68];
    __shared__ __align__(16) float ws[64][68];
    __shared__ float nrm[64];

    int bh = blockIdx.y;
    int b  = bh >> 3, h = bh & 7;
    int n0 = blockIdx.x * 64;
    int tid = threadIdx.x;
    int tx = tid & 15, ty = tid >> 4;

    #pragma unroll
    for (int r = 0; r < 4; r++) {
        int idx = tid + r*256;
        int c = idx >> 4, q = idx & 15;
        *(float4*)&ws[c][4*q] = *(const float4*)&g_wst[c*SLICE + 4*q];
    }
    const float* xbase = g_xmid + ((size_t)(b*NPIX + n0))*INNER + h*DH;
    #pragma unroll
    for (int r = 0; r < 4; r++) {
        int idx = tid + r*256;
        int j = idx >> 4, q = idx & 15;
        *(float4*)&xs[j][4*q] = *(const float4*)&xbase[(size_t)j*INNER + 4*q];
    }
    if (tid < 64) nrm[tid] = 0.f;
    __syncthreads();

    float o_[4][4];
    #pragma unroll
    for (int i = 0; i < 4; i++)
        #pragma unroll
        for (int j = 0; j < 4; j++) o_[i][j] = 0.f;

    #pragma unroll
    for (int k = 0; k < 64; k++) {
        float a0 = xs[ty*4+0][k], a1 = xs[ty*4+1][k];
        float a2 = xs[ty*4+2][k], a3 = xs[ty*4+3][k];
        float4 b4 = *(float4*)&ws[k][tx*4];
        o_[0][0] = fmaf(a0,b4.x,o_[0][0]); o_[0][1] = fmaf(a0,b4.y,o_[0][1]);
        o_[0][2] = fmaf(a0,b4.z,o_[0][2]); o_[0][3] = fmaf(a0,b4.w,o_[0][3]);
        o_[1][0] = fmaf(a1,b4.x,o_[1][0]); o_[1][1] = fmaf(a1,b4.y,o_[1][1]);
        o_[1][2] = fmaf(a1,b4.z,o_[1][2]); o_[1][3] = fmaf(a1,b4.w,o_[1][3]);
        o_[2][0] = fmaf(a2,b4.x,o_[2][0]); o_[2][1] = fmaf(a2,b4.y,o_[2][1]);
        o_[2][2] = fmaf(a2,b4.z,o_[2][2]); o_[2][3] = fmaf(a2,b4.w,o_[2][3]);
        o_[3][0] = fmaf(a3,b4.x,o_[3][0]); o_[3][1] = fmaf(a3,b4.y,o_[3][1]);
        o_[3][2] = fmaf(a3,b4.z,o_[3][2]); o_[3][3] = fmaf(a3,b4.w,o_[3][3]);
    }
    float t = temp_in[h];
    t = fminf(fmaxf(t, 0.1f), 5.0f);
    float invt = 1.f / t;
    __syncthreads();
    #pragma unroll
    for (int i = 0; i < 4; i++)
        #pragma unroll
        for (int j = 0; j < 4; j++)
            xs[ty*4+i][tx*4+j] = (o_[i][j] + bs[tx*4+j]) * invt;
    __syncthreads();

    int wid = tid >> 5, lane = tid & 31;
    float s0 = 0.f, s1 = 0.f;
    for (int r8 = 0; r8 < 8; r8++) {
        int row = wid*8 + r8;
        float v0 = xs[row][lane], v1 = xs[row][lane+32];
        float mx = fmaxf(v0, v1);
        #pragma unroll
        for (int off = 16; off; off >>= 1)
            mx = fmaxf(mx, __shfl_xor_sync(0xffffffffu, mx, off));
        float e0 = __expf(v0 - mx), e1 = __expf(v1 - mx);
        float sm = e0 + e1;
        #pragma unroll
        for (int off = 16; off; off >>= 1)
            sm += __shfl_xor_sync(0xffffffffu, sm, off);
        float inv = 1.f / sm;
        e0 *= inv; e1 *= inv;
        float* swp = g_sw + ((size_t)bh*NPIX + n0 + row)*SLICE;
        swp[lane] = e0; swp[lane+32] = e1;
        s0 += e0; s1 += e1;
    }
    atomicAdd(&nrm[lane],     s0);
    atomicAdd(&nrm[lane+32],  s1);
    __syncthreads();
    if (tid < 64) atomicAdd(&g_snorm[bh*SLICE + tid], nrm[tid]);
}

// ---------------- slice_token: tf32 mma, st = SW^T @ FX, 32-way K-split (verified win) ----------------
__global__ __launch_bounds__(256) void stoken_mm_kernel() {
    __shared__ __align__(16) float Asw[64][68];   // [n][g]
    __shared__ __align__(16) float Bfx[64][68];   // [n][c]
    int bh = blockIdx.y;
    int b  = bh >> 3, h = bh & 7;
    int n0 = blockIdx.x * 512;
    int tid = threadIdx.x;
    int wid = tid >> 5, lane = tid & 31;
    int g = lane >> 2, tig = lane & 3;
    int wm = wid >> 1, wn = wid & 1;

    float c[4][4];
    #pragma unroll
    for (int i = 0; i < 4; i++)
        #pragma unroll
        for (int q = 0; q < 4; q++) c[i][q] = 0.f;

    for (int nn = 0; nn < 512; nn += 64) {
        const float* swb = g_sw    + ((size_t)bh*NPIX + n0 + nn)*SLICE;
        const float* fxb = g_fxmid + ((size_t)(b*NPIX + n0 + nn))*INNER + h*DH;
        #pragma unroll
        for (int r = 0; r < 4; r++) {
            int op = tid + r*256;
            int row = op >> 4, q = op & 15;
            *(float4*)&Asw[row][4*q] = *(const float4*)&swb[(size_t)row*SLICE + 4*q];
            *(float4*)&Bfx[row][4*q] = *(const float4*)&fxb[(size_t)row*INNER + 4*q];
        }
        __syncthreads();
        #pragma unroll
        for (int ks = 0; ks < 8; ks++) {
            int k8 = ks*8;
            uint32_t a[4];
            int r0 = wm*16 + g;
            a[0] = __float_as_uint(Asw[k8 + tig    ][r0]);
            a[1] = __float_as_uint(Asw[k8 + tig    ][r0 + 8]);
            a[2] = __float_as_uint(Asw[k8 + tig + 4][r0]);
            a[3] = __float_as_uint(Asw[k8 + tig + 4][r0 + 8]);
            #pragma unroll
            for (int nti = 0; nti < 4; nti++) {
                uint32_t bf[2];
                int col = wn*32 + nti*8 + g;
                bf[0] = __float_as_uint(Bfx[k8 + tig    ][col]);
                bf[1] = __float_as_uint(Bfx[k8 + tig + 4][col]);
                mma_tf32_16x8x8(c[nti], a, bf);
            }
        }
        __syncthreads();
    }
    int r0 = wm*16 + g;
    #pragma unroll
    for (int nti = 0; nti < 4; nti++) {
        int col = wn*32 + nti*8 + tig*2;
        float* stp = g_stok + bh*4096;
        atomicAdd(&stp[ r0   *64 + col  ], c[nti][0]);
        atomicAdd(&stp[ r0   *64 + col+1], c[nti][1]);
        atomicAdd(&stp[(r0+8)*64 + col  ], c[nti][2]);
        atomicAdd(&stp[(r0+8)*64 + col+1], c[nti][3]);
    }
}

// ---------------- tiny M x M attention per (b,h) ----------------
#define AT_LD 68
#define ATTN_SMEM (5*64*AT_LD*4)
__global__ __launch_bounds__(256) void attn_kernel(const float* __restrict__ Wq,
                                                   const float* __restrict__ Wk,
                                                   const float* __restrict__ Wv) {
    extern __shared__ float smb[];
    float* tok = smb;
    float* wsm = smb + 1*64*AT_LD;
    float* qs  = smb + 2*64*AT_LD;
    float* ks_ = smb + 3*64*AT_LD;
    float* vs  = smb + 4*64*AT_LD;

    int bh  = blockIdx.x;
    int tid = threadIdx.x;

    for (int e = tid; e < 4096; e += 256) {
        int g = e >> 6, c = e & 63;
        float nm = g_snorm[bh*SLICE + g] + 1e-5f;
        tok[g*AT_LD + c] = g_stok[bh*4096 + e] / nm;
    }
    __syncthreads();

    #pragma unroll
    for (int w = 0; w < 3; w++) {
        const float* W = (w == 0) ? Wq : (w == 1) ? Wk : Wv;
        float* dst     = (w == 0) ? qs : (w == 1) ? ks_ : vs;
        for (int e = tid; e < 4096; e += 256)
            wsm[(e >> 6)*AT_LD + (e & 63)] = W[e];
        __syncthreads();
        for (int e = tid; e < 4096; e += 256) {
            int g = e >> 6, d = e & 63;
            float s = 0.f;
            #pragma unroll 8
            for (int c = 0; c < 64; c++)
                s = fmaf(tok[g*AT_LD + c], wsm[d*AT_LD + c], s);
            dst[g*AT_LD + d] = s;
        }
        __syncthreads();
    }
    for (int e = tid; e < 4096; e += 256) {
        int g = e >> 6, j = e & 63;
        float s = 0.f;
        #pragma unroll 8
        for (int d = 0; d < 64; d++)
            s = fmaf(qs[g*AT_LD + d], ks_[j*AT_LD + d], s);
        tok[g*AT_LD + j] = s * 0.125f;
    }
    __syncthreads();
    int wid = tid >> 5, lane = tid & 31;
    for (int r8 = 0; r8 < 8; r8++) {
        int row = wid*8 + r8;
        float v0 = tok[row*AT_LD + lane], v1 = tok[row*AT_LD + lane + 32];
        float mx = fmaxf(v0, v1);
        #pragma unroll
        for (int off = 16; off; off >>= 1)
            mx = fmaxf(mx, __shfl_xor_sync(0xffffffffu, mx, off));
        float e0 = __expf(v0 - mx), e1 = __expf(v1 - mx);
        float sm = e0 + e1;
        #pragma unroll
        for (int off = 16; off; off >>= 1)
            sm += __shfl_xor_sync(0xffffffffu, sm, off);
        float inv = 1.f / sm;
        tok[row*AT_LD + lane]      = e0 * inv;
        tok[row*AT_LD + lane + 32] = e1 * inv;
    }
    __syncthreads();
    for (int e = tid; e < 4096; e += 256) {
        int g = e >> 6, d = e & 63;
        float s = 0.f;
        #pragma unroll 8
        for (int j = 0; j < 64; j++)
            s = fmaf(tok[g*AT_LD + j], vs[j*AT_LD + d], s);
        g_osl[bh*4096 + e] = s;
    }
}

// ---------------- fused scatter-back + Wo projection (round-3 proven) ----------------
#define OUT_SMEM (3*64*68*4 + 64*132*4)
__global__ __launch_bounds__(256) void out_kernel(const float* __restrict__ bo,
                                                  float* __restrict__ out) {
    extern __shared__ float smb[];
    float* sws = smb;
    float* oss = smb + 1*64*68;
    float* oxs = smb + 2*64*68;
    float* wos = smb + 3*64*68;

    int m0 = blockIdx.x * 64;
    int b  = m0 >> 14;
    int nl = m0 & (NPIX - 1);
    int tid = threadIdx.x;
    int tx = tid & 15, ty = tid >> 4;

    float acc[4][8];
    #pragma unroll
    for (int i = 0; i < 4; i++)
        #pragma unroll
        for (int j = 0; j < 8; j++) acc[i][j] = 0.f;

    for (int h = 0; h < HEADS; h++) {
        int bh = b*HEADS + h;
        const float* swb = g_sw  + ((size_t)bh*NPIX + nl)*SLICE;
        const float* osb = g_osl + bh*4096;
        const float* wob = g_wot + h*DH*DIM;
        #pragma unroll
        for (int r = 0; r < 4; r++) {
            int idx = tid + r*256;
            int j = idx >> 4, q = idx & 15;
            *(float4*)&sws[j*68 + 4*q] = *(const float4*)&swb[(size_t)j*SLICE + 4*q];
            *(float4*)&oss[j*68 + 4*q] = *(const float4*)&osb[j*64 + 4*q];
        }
        #pragma unroll
        for (int r = 0; r < 8; r++) {
            int idx = tid + r*256;
            int c = idx >> 5, q = idx & 31;
            *(float4*)&wos[c*132 + 4*q] = *(const float4*)&wob[c*DIM + 4*q];
        }
        __syncthreads();
        float t_[4][4];
        #pragma unroll
        for (int i = 0; i < 4; i++)
            #pragma unroll
            for (int j = 0; j < 4; j++) t_[i][j] = 0.f;
        #pragma unroll
        for (int k = 0; k < 64; k++) {
            float a0 = sws[(ty*4+0)*68 + k], a1 = sws[(ty*4+1)*68 + k];
            float a2 = sws[(ty*4+2)*68 + k], a3 = sws[(ty*4+3)*68 + k];
            float4 b4 = *(float4*)&oss[k*68 + tx*4];
            t_[0][0]=fmaf(a0,b4.x,t_[0][0]); t_[0][1]=fmaf(a0,b4.y,t_[0][1]);
            t_[0][2]=fmaf(a0,b4.z,t_[0][2]); t_[0][3]=fmaf(a0,b4.w,t_[0][3]);
            t_[1][0]=fmaf(a1,b4.x,t_[1][0]); t_[1][1]=fmaf(a1,b4.y,t_[1][1]);
            t_[1][2]=fmaf(a1,b4.z,t_[1][2]); t_[1][3]=fmaf(a1,b4.w,t_[1][3]);
            t_[2][0]=fmaf(a2,b4.x,t_[2][0]); t_[2][1]=fmaf(a2,b4.y,t_[2][1]);
            t_[2][2]=fmaf(a2,b4.z,t_[2][2]); t_[2][3]=fmaf(a2,b4.w,t_[2][3]);
            t_[3][0]=fmaf(a3,b4.x,t_[3][0]); t_[3][1]=fmaf(a3,b4.y,t_[3][1]);
            t_[3][2]=fmaf(a3,b4.z,t_[3][2]); t_[3][3]=fmaf(a3,b4.w,t_[3][3]);
        }
        #pragma unroll
        for (int i = 0; i < 4; i++) {
            float4 v; v.x = t_[i][0]; v.y = t_[i][1]; v.z = t_[i][2]; v.w = t_[i][3];
            *(float4*)&oxs[(ty*4+i)*68 + tx*4] = v;
        }
        __syncthreads();
        #pragma unroll
        for (int k = 0; k < 64; k++) {
            float a0 = oxs[(ty*4+0)*68 + k], a1 = oxs[(ty*4+1)*68 + k];
            float a2 = oxs[(ty*4+2)*68 + k], a3 = oxs[(ty*4+3)*68 + k];
            float4 b0 = *(float4*)&wos[k*132 + tx*8];
            float4 b1 = *(float4*)&wos[k*132 + tx*8 + 4];
            float bb[8] = {b0.x,b0.y,b0.z,b0.w,b1.x,b1.y,b1.z,b1.w};
            float aa[4] = {a0,a1,a2,a3};
            #pragma unroll
            for (int i = 0; i < 4; i++)
                #pragma unroll
                for (int j = 0; j < 8; j++)
                    acc[i][j] = fmaf(aa[i], bb[j], acc[i][j]);
        }
        __syncthreads();
    }
    #pragma unroll
    for (int i = 0; i < 4; i++) {
        int m = m0 + ty*4 + i;
        float4 v0, v1;
        v0.x = acc[i][0] + bo[tx*8+0]; v0.y = acc[i][1] + bo[tx*8+1];
        v0.z = acc[i][2] + bo[tx*8+2]; v0.w = acc[i][3] + bo[tx*8+3];
        v1.x = acc[i][4] + bo[tx*8+4]; v1.y = acc[i][5] + bo[tx*8+5];
        v1.z = acc[i][6] + bo[tx*8+6]; v1.w = acc[i][7] + bo[tx*8+7];
        *(float4*)&out[(size_t)m*DIM + tx*8]     = v0;
        *(float4*)&out[(size_t)m*DIM + tx*8 + 4] = v1;
    }
}

// ---------------- launch ----------------
extern "C" void kernel_launch(void* const* d_in, const int* in_sizes, int n_in,
                              void* d_out, int out_size) {
    const float* x           = (const float*)d_in[0];
    const float* temperature = (const float*)d_in[1];
    const float* Wx          = (const float*)d_in[2];
    const float* bx          = (const float*)d_in[3];
    const float* Wfx         = (const float*)d_in[4];
    const float* bfx         = (const float*)d_in[5];
    const float* Ws          = (const float*)d_in[6];
    const float* bs          = (const float*)d_in[7];
    const float* Wq          = (const float*)d_in[8];
    const float* Wk          = (const float*)d_in[9];
    const float* Wv          = (const float*)d_in[10];
    const float* Wo          = (const float*)d_in[11];
    const float* bo          = (const float*)d_in[12];
    float* out = (float*)d_out;

    cudaFuncSetAttribute(conv_mm_kernel, cudaFuncAttributeMaxDynamicSharedMemorySize, CONV_DSMEM);
    cudaFuncSetAttribute(attn_kernel, cudaFuncAttributeMaxDynamicSharedMemorySize, ATTN_SMEM);
    cudaFuncSetAttribute(out_kernel,  cudaFuncAttributeMaxDynamicSharedMemorySize, OUT_SMEM);

    prep_kernel<<<2048, 256>>>(x, Wx, Wfx, Ws, Wo);
    conv_mm_kernel<<<dim3(M_TOT/128, 4, 2), 256, CONV_DSMEM>>>(bx, bfx);
    logits_kernel<<<dim3(NPIX/64, BATCH*HEADS), 256>>>(bs, temperature);
    stoken_mm_kernel<<<dim3(NPIX/512, BATCH*HEADS), 256>>>();
    attn_kernel<<<BATCH*HEADS, 256, ATTN_SMEM>>>(Wq, Wk, Wv);
    out_kernel<<<M_TOT/64, 256, OUT_SMEM>>>(bo, out);
}

// round 8
// speedup vs baseline: 1.4793x; 1.2269x over previous
#include <cuda_runtime.h>
#include <math.h>
#include <stdint.h>

#define BATCH  4
#define HEIGHT 128
#define WIDTH  128
#define NPIX   (HEIGHT*WIDTH)      // 16384
#define M_TOT  (BATCH*NPIX)        // 65536
#define DIM    128
#define HEADS  8
#define DH     64
#define INNER  512
#define SLICE  64

// ---------------- scratch (device globals; no allocations) ----------------
__device__ float g_xr  [(size_t)M_TOT*DIM];    // tf32-rounded input [pix][c]
__device__ float g_wb  [18*INNER*DIM];         // conv weights per tap: [pt][o][ci], tf32
__device__ float g_wst [DH*SLICE];             // Ws^T: [c][g]
__device__ float g_xmid [(size_t)M_TOT*INNER]; // conv_x  out (tf32-rounded)
__device__ float g_fxmid[(size_t)M_TOT*INNER]; // conv_fx out (tf32-rounded)
__device__ float g_sw   [(size_t)BATCH*HEADS*NPIX*SLICE];  // tf32-rounded
__device__ float g_snorm[BATCH*HEADS*SLICE];
__device__ float g_stok [BATCH*HEADS*SLICE*DH];
__device__ float g_osl  [BATCH*HEADS*SLICE*DH];
__device__ float g_pt   [BATCH*DIM*INNER];     // P^T: [b][o][h*64+g] (tf32-rounded)

// ---------------- helpers ----------------
__device__ __forceinline__ float tf32r(float f) {
    uint32_t u;
    asm("cvt.rna.tf32.f32 %0, %1;" : "=r"(u) : "f"(f));
    return __uint_as_float(u);
}
__device__ __forceinline__ void cpa16(uint32_t dst, const void* src, int sz) {
    asm volatile("cp.async.cg.shared.global [%0], [%1], 16, %2;" :: "r"(dst), "l"(src), "r"(sz));
}
#define CP_COMMIT() asm volatile("cp.async.commit_group;" ::: "memory")
#define CP_WAIT2()  asm volatile("cp.async.wait_group 2;" ::: "memory")
__device__ __forceinline__ uint32_t smem_u32(const void* p) {
    uint32_t a;
    asm("{ .reg .u64 t; cvta.to.shared.u64 t, %1; cvt.u32.u64 %0, t; }" : "=r"(a) : "l"(p));
    return a;
}
__device__ __forceinline__ void mma_tf32_16x8x8(float* c, const uint32_t* a, const uint32_t* b) {
    asm volatile("mma.sync.aligned.m16n8k8.row.col.f32.tf32.tf32.f32 "
        "{%0,%1,%2,%3}, {%4,%5,%6,%7}, {%8,%9}, {%0,%1,%2,%3};"
        : "+f"(c[0]), "+f"(c[1]), "+f"(c[2]), "+f"(c[3])
        : "r"(a[0]), "r"(a[1]), "r"(a[2]), "r"(a[3]), "r"(b[0]), "r"(b[1]));
}
__device__ __forceinline__ void ldsm_x4(uint32_t* r, uint32_t addr) {
    asm volatile("ldmatrix.sync.aligned.m8n8.x4.shared.b16 {%0,%1,%2,%3}, [%4];"
        : "=r"(r[0]), "=r"(r[1]), "=r"(r[2]), "=r"(r[3]) : "r"(addr));
}

// ---------------- prep ----------------
__global__ void prep_kernel(const float* __restrict__ x,
                            const float* __restrict__ Wx, const float* __restrict__ Wfx,
                            const float* __restrict__ Ws) {
    int stride = gridDim.x * blockDim.x;
    int tid = blockIdx.x * blockDim.x + threadIdx.x;
    for (size_t t = tid; t < (size_t)M_TOT*DIM; t += stride)
        g_xr[t] = tf32r(x[t]);
    for (int t = tid; t < 18*INNER*DIM; t += stride) {
        int ci = t & 127;
        int o  = (t >> 7) & 511;
        int pt = t >> 16;
        int conv = pt / 9, p = pt % 9;
        int ky = p / 3, kx = p % 3;
        const float* W = conv ? Wfx : Wx;
        g_wb[t] = tf32r(W[((o*DIM + ci)*3 + ky)*3 + kx]);
    }
    for (int t = tid; t < DH*SLICE; t += stride) {
        int g = t >> 6, c = t & 63;
        g_wst[c*SLICE + g] = Ws[g*DH + c];
    }
    for (int t = tid; t < BATCH*HEADS*SLICE; t += stride)    g_snorm[t] = 0.f;
    for (int t = tid; t < BATCH*HEADS*SLICE*DH; t += stride) g_stok[t]  = 0.f;
}

// ---------------- tf32 mma conv: CTA 128x128, warp 32x64, K-chunk 32, ldmatrix ----------------
#define ALD 36
#define STAGE_FLOATS (128*ALD)
#define CONV_DSMEM (6*STAGE_FLOATS*4)        // 110592 B
#define NCHUNK 36

__device__ __forceinline__ void load_chunk_mm(int j, float* sA, float* sB, int tid,
                                              int b, int y, int o0, const float* wt) {
    int p  = j >> 2;
    int c0 = (j & 3) * 32;
    int ky = p / 3, kx = p % 3;
    int yy = y + ky - 1;
    bool rowok = ((unsigned)yy < (unsigned)HEIGHT);
    int yys = rowok ? yy : 0;
    uint32_t sa = smem_u32(sA), sb = smem_u32(sB);
    #pragma unroll
    for (int r = 0; r < 4; r++) {
        int op = tid + r*256;
        int row = op >> 3, q = op & 7;
        int gx = row + kx - 1;
        bool ok = rowok && ((unsigned)gx < (unsigned)WIDTH);
        const float* src = g_xr + ((size_t)((b*HEIGHT + yys)*WIDTH + (ok ? gx : 0)))*DIM + c0 + q*4;
        cpa16(sa + (row*ALD + q*4)*4, src, ok ? 16 : 0);
    }
    #pragma unroll
    for (int r = 0; r < 4; r++) {
        int op = tid + r*256;
        int row = op >> 3, q = op & 7;
        const float* src = wt + ((size_t)(p*INNER + o0 + row))*DIM + c0 + q*4;
        cpa16(sb + (row*ALD + q*4)*4, src, 16);
    }
}

__global__ __launch_bounds__(256) void conv_mm_kernel(const float* __restrict__ bx,
                                                      const float* __restrict__ bfx) {
    extern __shared__ float smb[];
    float* sA = smb;
    float* sB = smb + 3*STAGE_FLOATS;

    int mt = blockIdx.x;
    int b  = mt >> 7, y = mt & 127;
    int m0 = mt * 128;
    int o0 = blockIdx.y * 128;
    int conv = blockIdx.z;
    const float* wt = g_wb + (size_t)conv*9*INNER*DIM;

    int tid  = threadIdx.x;
    int wid  = tid >> 5, lane = tid & 31;
    int g    = lane >> 2, tig = lane & 3;
    int wm   = wid >> 1, wn = wid & 1;

    int lrow = lane & 15;
    int lcol = (lane >> 4) * 4;
    uint32_t aOff = ((wm*32 + lrow)*ALD + lcol) * 4;
    uint32_t bOff = ((wn*64 + lrow)*ALD + lcol) * 4;

    float c[2][8][4];
    #pragma unroll
    for (int i = 0; i < 2; i++)
        #pragma unroll
        for (int j = 0; j < 8; j++)
            #pragma unroll
            for (int q = 0; q < 4; q++) c[i][j][q] = 0.f;

    load_chunk_mm(0, sA, sB, tid, b, y, o0, wt); CP_COMMIT();
    load_chunk_mm(1, sA + STAGE_FLOATS, sB + STAGE_FLOATS, tid, b, y, o0, wt); CP_COMMIT();

    for (int it = 0; it < NCHUNK; ++it) {
        int j = it + 2;
        if (j < NCHUNK) {
            int s2 = j % 3;
            load_chunk_mm(j, sA + s2*STAGE_FLOATS, sB + s2*STAGE_FLOATS, tid, b, y, o0, wt);
        }
        CP_COMMIT();
        CP_WAIT2();
        __syncthreads();

        uint32_t saU = smem_u32(sA + (it % 3)*STAGE_FLOATS) + aOff;
        uint32_t sbU = smem_u32(sB + (it % 3)*STAGE_FLOATS) + bOff;
        #pragma unroll
        for (int ks = 0; ks < 4; ks++) {
            uint32_t k8b = ks*8*4;
            uint32_t a[2][4];
            ldsm_x4(a[0], saU + k8b);
            ldsm_x4(a[1], saU + 16*ALD*4 + k8b);
            uint32_t bf[8][2];
            #pragma unroll
            for (int pr = 0; pr < 4; pr++) {
                uint32_t t4[4];
                ldsm_x4(t4, sbU + pr*16*ALD*4 + k8b);
                bf[2*pr  ][0] = t4[0]; bf[2*pr+1][0] = t4[1];
                bf[2*pr  ][1] = t4[2]; bf[2*pr+1][1] = t4[3];
            }
            #pragma unroll
            for (int mti = 0; mti < 2; mti++)
                #pragma unroll
                for (int nti = 0; nti < 8; nti++)
                    mma_tf32_16x8x8(c[mti][nti], a[mti], bf[nti]);
        }
        __syncthreads();
    }

    float* outp = conv ? g_fxmid : g_xmid;
    const float* bias = conv ? bfx : bx;
    #pragma unroll
    for (int mti = 0; mti < 2; mti++) {
        int r0 = m0 + wm*32 + mti*16 + g;
        #pragma unroll
        for (int nti = 0; nti < 8; nti++) {
            int oc = o0 + wn*64 + nti*8 + tig*2;
            float b0 = bias[oc], b1 = bias[oc+1];
            float2 v0, v1;
            v0.x = tf32r(c[mti][nti][0] + b0); v0.y = tf32r(c[mti][nti][1] + b1);
            v1.x = tf32r(c[mti][nti][2] + b0); v1.y = tf32r(c[mti][nti][3] + b1);
            *(float2*)&outp[(size_t) r0   *INNER + oc] = v0;
            *(float2*)&outp[(size_t)(r0+8)*INNER + oc] = v1;
        }
    }
}

// ---------------- logits GEMM + softmax + partial slice_norm (round-3 proven) ----------------
__global__ __launch_bounds__(256) void logits_kernel(const float* __restrict__ bs,
                                                     const float* __restrict__ temp_in) {
    __shared__ __align__(16) float xs[64][68];
    __shared__ __align__(16) float ws[64][68];
    __shared__ float nrm[64];

    int bh = blockIdx.y;
    int b  = bh >> 3, h = bh & 7;
    int n0 = blockIdx.x * 64;
    int tid = threadIdx.x;
    int tx = tid & 15, ty = tid >> 4;

    #pragma unroll
    for (int r = 0; r < 4; r++) {
        int idx = tid + r*256;
        int c = idx >> 4, q = idx & 15;
        *(float4*)&ws[c][4*q] = *(const float4*)&g_wst[c*SLICE + 4*q];
    }
    const float* xbase = g_xmid + ((size_t)(b*NPIX + n0))*INNER + h*DH;
    #pragma unroll
    for (int r = 0; r < 4; r++) {
        int idx = tid + r*256;
        int j = idx >> 4, q = idx & 15;
        *(float4*)&xs[j][4*q] = *(const float4*)&xbase[(size_t)j*INNER + 4*q];
    }
    if (tid < 64) nrm[tid] = 0.f;
    __syncthreads();

    float o_[4][4];
    #pragma unroll
    for (int i = 0; i < 4; i++)
        #pragma unroll
        for (int j = 0; j < 4; j++) o_[i][j] = 0.f;

    #pragma unroll
    for (int k = 0; k < 64; k++) {
        float a0 = xs[ty*4+0][k], a1 = xs[ty*4+1][k];
        float a2 = xs[ty*4+2][k], a3 = xs[ty*4+3][k];
        float4 b4 = *(float4*)&ws[k][tx*4];
        o_[0][0] = fmaf(a0,b4.x,o_[0][0]); o_[0][1] = fmaf(a0,b4.y,o_[0][1]);
        o_[0][2] = fmaf(a0,b4.z,o_[0][2]); o_[0][3] = fmaf(a0,b4.w,o_[0][3]);
        o_[1][0] = fmaf(a1,b4.x,o_[1][0]); o_[1][1] = fmaf(a1,b4.y,o_[1][1]);
        o_[1][2] = fmaf(a1,b4.z,o_[1][2]); o_[1][3] = fmaf(a1,b4.w,o_[1][3]);
        o_[2][0] = fmaf(a2,b4.x,o_[2][0]); o_[2][1] = fmaf(a2,b4.y,o_[2][1]);
        o_[2][2] = fmaf(a2,b4.z,o_[2][2]); o_[2][3] = fmaf(a2,b4.w,o_[2][3]);
        o_[3][0] = fmaf(a3,b4.x,o_[3][0]); o_[3][1] = fmaf(a3,b4.y,o_[3][1]);
        o_[3][2] = fmaf(a3,b4.z,o_[3][2]); o_[3][3] = fmaf(a3,b4.w,o_[3][3]);
    }
    float t = temp_in[h];
    t = fminf(fmaxf(t, 0.1f), 5.0f);
    float invt = 1.f / t;
    __syncthreads();
    #pragma unroll
    for (int i = 0; i < 4; i++)
        #pragma unroll
        for (int j = 0; j < 4; j++)
            xs[ty*4+i][tx*4+j] = (o_[i][j] + bs[tx*4+j]) * invt;
    __syncthreads();

    int wid = tid >> 5, lane = tid & 31;
    float s0 = 0.f, s1 = 0.f;
    for (int r8 = 0; r8 < 8; r8++) {
        int row = wid*8 + r8;
        float v0 = xs[row][lane], v1 = xs[row][lane+32];
        float mx = fmaxf(v0, v1);
        #pragma unroll
        for (int off = 16; off; off >>= 1)
            mx = fmaxf(mx, __shfl_xor_sync(0xffffffffu, mx, off));
        float e0 = __expf(v0 - mx), e1 = __expf(v1 - mx);
        float sm = e0 + e1;
        #pragma unroll
        for (int off = 16; off; off >>= 1)
            sm += __shfl_xor_sync(0xffffffffu, sm, off);
        float inv = 1.f / sm;
        e0 *= inv; e1 *= inv;
        float* swp = g_sw + ((size_t)bh*NPIX + n0 + row)*SLICE;
        swp[lane]      = tf32r(e0);
        swp[lane + 32] = tf32r(e1);
        s0 += e0; s1 += e1;
    }
    atomicAdd(&nrm[lane],     s0);
    atomicAdd(&nrm[lane+32],  s1);
    __syncthreads();
    if (tid < 64) atomicAdd(&g_snorm[bh*SLICE + tid], nrm[tid]);
}

// ---------------- slice_token: tf32 mma, st = SW^T @ FX, 32-way K-split ----------------
__global__ __launch_bounds__(256) void stoken_mm_kernel() {
    __shared__ __align__(16) float Asw[64][68];   // [n][g]
    __shared__ __align__(16) float Bfx[64][68];   // [n][c]
    int bh = blockIdx.y;
    int b  = bh >> 3, h = bh & 7;
    int n0 = blockIdx.x * 512;
    int tid = threadIdx.x;
    int wid = tid >> 5, lane = tid & 31;
    int g = lane >> 2, tig = lane & 3;
    int wm = wid >> 1, wn = wid & 1;

    float c[4][4];
    #pragma unroll
    for (int i = 0; i < 4; i++)
        #pragma unroll
        for (int q = 0; q < 4; q++) c[i][q] = 0.f;

    for (int nn = 0; nn < 512; nn += 64) {
        const float* swb = g_sw    + ((size_t)bh*NPIX + n0 + nn)*SLICE;
        const float* fxb = g_fxmid + ((size_t)(b*NPIX + n0 + nn))*INNER + h*DH;
        #pragma unroll
        for (int r = 0; r < 4; r++) {
            int op = tid + r*256;
            int row = op >> 4, q = op & 15;
            *(float4*)&Asw[row][4*q] = *(const float4*)&swb[(size_t)row*SLICE + 4*q];
            *(float4*)&Bfx[row][4*q] = *(const float4*)&fxb[(size_t)row*INNER + 4*q];
        }
        __syncthreads();
        #pragma unroll
        for (int ks = 0; ks < 8; ks++) {
            int k8 = ks*8;
            uint32_t a[4];
            int r0 = wm*16 + g;
            a[0] = __float_as_uint(Asw[k8 + tig    ][r0]);
            a[1] = __float_as_uint(Asw[k8 + tig    ][r0 + 8]);
            a[2] = __float_as_uint(Asw[k8 + tig + 4][r0]);
            a[3] = __float_as_uint(Asw[k8 + tig + 4][r0 + 8]);
            #pragma unroll
            for (int nti = 0; nti < 4; nti++) {
                uint32_t bf[2];
                int col = wn*32 + nti*8 + g;
                bf[0] = __float_as_uint(Bfx[k8 + tig    ][col]);
                bf[1] = __float_as_uint(Bfx[k8 + tig + 4][col]);
                mma_tf32_16x8x8(c[nti], a, bf);
            }
        }
        __syncthreads();
    }
    int r0 = wm*16 + g;
    #pragma unroll
    for (int nti = 0; nti < 4; nti++) {
        int col = wn*32 + nti*8 + tig*2;
        float* stp = g_stok + bh*4096;
        atomicAdd(&stp[ r0   *64 + col  ], c[nti][0]);
        atomicAdd(&stp[ r0   *64 + col+1], c[nti][1]);
        atomicAdd(&stp[(r0+8)*64 + col  ], c[nti][2]);
        atomicAdd(&stp[(r0+8)*64 + col+1], c[nti][3]);
    }
}

// ---------------- tiny M x M attention per (b,h) ----------------
#define AT_LD 68
#define ATTN_SMEM (5*64*AT_LD*4)
__global__ __launch_bounds__(256) void attn_kernel(const float* __restrict__ Wq,
                                                   const float* __restrict__ Wk,
                                                   const float* __restrict__ Wv) {
    extern __shared__ float smb[];
    float* tok = smb;
    float* wsm = smb + 1*64*AT_LD;
    float* qs  = smb + 2*64*AT_LD;
    float* ks_ = smb + 3*64*AT_LD;
    float* vs  = smb + 4*64*AT_LD;

    int bh  = blockIdx.x;
    int tid = threadIdx.x;

    for (int e = tid; e < 4096; e += 256) {
        int g = e >> 6, c = e & 63;
        float nm = g_snorm[bh*SLICE + g] + 1e-5f;
        tok[g*AT_LD + c] = g_stok[bh*4096 + e] / nm;
    }
    __syncthreads();

    #pragma unroll
    for (int w = 0; w < 3; w++) {
        const float* W = (w == 0) ? Wq : (w == 1) ? Wk : Wv;
        float* dst     = (w == 0) ? qs : (w == 1) ? ks_ : vs;
        for (int e = tid; e < 4096; e += 256)
            wsm[(e >> 6)*AT_LD + (e & 63)] = W[e];
        __syncthreads();
        for (int e = tid; e < 4096; e += 256) {
            int g = e >> 6, d = e & 63;
            float s = 0.f;
            #pragma unroll 8
            for (int c = 0; c < 64; c++)
                s = fmaf(tok[g*AT_LD + c], wsm[d*AT_LD + c], s);
            dst[g*AT_LD + d] = s;
        }
        __syncthreads();
    }
    for (int e = tid; e < 4096; e += 256) {
        int g = e >> 6, j = e & 63;
        float s = 0.f;
        #pragma unroll 8
        for (int d = 0; d < 64; d++)
            s = fmaf(qs[g*AT_LD + d], ks_[j*AT_LD + d], s);
        tok[g*AT_LD + j] = s * 0.125f;
    }
    __syncthreads();
    int wid = tid >> 5, lane = tid & 31;
    for (int r8 = 0; r8 < 8; r8++) {
        int row = wid*8 + r8;
        float v0 = tok[row*AT_LD + lane], v1 = tok[row*AT_LD + lane + 32];
        float mx = fmaxf(v0, v1);
        #pragma unroll
        for (int off = 16; off; off >>= 1)
            mx = fmaxf(mx, __shfl_xor_sync(0xffffffffu, mx, off));
        float e0 = __expf(v0 - mx), e1 = __expf(v1 - mx);
        float sm = e0 + e1;
        #pragma unroll
        for (int off = 16; off; off >>= 1)
            sm += __shfl_xor_sync(0xffffffffu, sm, off);
        float inv = 1.f / sm;
        tok[row*AT_LD + lane]      = e0 * inv;
        tok[row*AT_LD + lane + 32] = e1 * inv;
    }
    __syncthreads();
    for (int e = tid; e < 4096; e += 256) {
        int g = e >> 6, d = e & 63;
        float s = 0.f;
        #pragma unroll 8
        for (int j = 0; j < 64; j++)
            s = fmaf(tok[g*AT_LD + j], vs[j*AT_LD + d], s);
        g_osl[bh*4096 + e] = s;
    }
}

// ---------------- pproj: P^T[b][o][h*64+g] = sum_c osl[bh][g][c] * Wo[o][h*64+c] ----------------
__global__ __launch_bounds__(256) void pproj_kernel(const float* __restrict__ Wo) {
    __shared__ float sosl[64][65];
    __shared__ float swo [128][65];
    int bh = blockIdx.x;
    int b  = bh >> 3, h = bh & 7;
    int tid = threadIdx.x;

    for (int e = tid; e < 4096; e += 256) {
        int g = e >> 6, c = e & 63;
        sosl[g][c] = g_osl[bh*4096 + e];
    }
    for (int e = tid; e < 8192; e += 256) {
        int o = e >> 6, c = e & 63;
        swo[o][c] = Wo[o*INNER + h*DH + c];
    }
    __syncthreads();
    for (int e = tid; e < 8192; e += 256) {
        int o = e >> 6, g = e & 63;
        float s = 0.f;
        #pragma unroll 8
        for (int c = 0; c < 64; c++)
            s = fmaf(sosl[g][c], swo[o][c], s);
        g_pt[(b*DIM + o)*INNER + h*DH + g] = tf32r(s);
    }
}

// ---------------- out GEMM: out_b = SW_b (16384x512) @ P_b^T (512x128), tf32 mma ----------------
__global__ __launch_bounds__(256) void outgemm_kernel(const float* __restrict__ bo,
                                                      float* __restrict__ out) {
    extern __shared__ float smb[];
    float* sA = smb;
    float* sB = smb + 3*STAGE_FLOATS;

    int n0 = blockIdx.x * 128;
    int b  = blockIdx.y;
    int tid  = threadIdx.x;
    int wid  = tid >> 5, lane = tid & 31;
    int g    = lane >> 2, tig = lane & 3;
    int wm   = wid >> 1, wn = wid & 1;

    float c[2][8][4];
    #pragma unroll
    for (int i = 0; i < 2; i++)
        #pragma unroll
        for (int j = 0; j < 8; j++)
            #pragma unroll
            for (int q = 0; q < 4; q++) c[i][j][q] = 0.f;

    auto load_chunk = [&](int kk, float* dA, float* dB) {
        int h  = kk >> 1;
        int g0 = (kk & 1) * 32;
        uint32_t sa = smem_u32(dA), sb = smem_u32(dB);
        #pragma unroll
        for (int r = 0; r < 4; r++) {
            int op = tid + r*256;
            int row = op >> 3, q = op & 7;
            const float* srcA = g_sw + ((size_t)((b*HEADS + h)*NPIX) + n0 + row)*SLICE + g0 + q*4;
            cpa16(sa + (row*ALD + q*4)*4, srcA, 16);
            const float* srcB = g_pt + (size_t)(b*DIM + row)*INNER + kk*32 + q*4;
            cpa16(sb + (row*ALD + q*4)*4, srcB, 16);
        }
    };

    load_chunk(0, sA, sB); CP_COMMIT();
    load_chunk(1, sA + STAGE_FLOATS, sB + STAGE_FLOATS); CP_COMMIT();

    for (int it = 0; it < 16; ++it) {
        int j = it + 2;
        if (j < 16) {
            int s2 = j % 3;
            load_chunk(j, sA + s2*STAGE_FLOATS, sB + s2*STAGE_FLOATS);
        }
        CP_COMMIT();
        CP_WAIT2();
        __syncthreads();

        const float* As = sA + (it % 3)*STAGE_FLOATS;
        const float* Bs = sB + (it % 3)*STAGE_FLOATS;
        #pragma unroll
        for (int ks = 0; ks < 4; ks++) {
            int k8 = ks*8;
            uint32_t a[2][4];
            #pragma unroll
            for (int mti = 0; mti < 2; mti++) {
                int r0 = wm*32 + mti*16 + g;
                a[mti][0] = __float_as_uint(As[ r0    *ALD + k8 + tig]);
                a[mti][1] = __float_as_uint(As[(r0+8) *ALD + k8 + tig]);
                a[mti][2] = __float_as_uint(As[ r0    *ALD + k8 + tig + 4]);
                a[mti][3] = __float_as_uint(As[(r0+8) *ALD + k8 + tig + 4]);
            }
            uint32_t bf[8][2];
            #pragma unroll
            for (int nti = 0; nti < 8; nti++) {
                int n = wn*64 + nti*8 + g;
                bf[nti][0] = __float_as_uint(Bs[n*ALD + k8 + tig]);
                bf[nti][1] = __float_as_uint(Bs[n*ALD + k8 + tig + 4]);
            }
            #pragma unroll
            for (int mti = 0; mti < 2; mti++)
                #pragma unroll
                for (int nti = 0; nti < 8; nti++)
                    mma_tf32_16x8x8(c[mti][nti], a[mti], bf[nti]);
        }
        __syncthreads();
    }

    #pragma unroll
    for (int mti = 0; mti < 2; mti++) {
        int r0 = b*NPIX + n0 + wm*32 + mti*16 + g;
        #pragma unroll
        for (int nti = 0; nti < 8; nti++) {
            int oc = wn*64 + nti*8 + tig*2;
            float b0 = bo[oc], b1 = bo[oc+1];
            float2 v0, v1;
            v0.x = c[mti][nti][0] + b0; v0.y = c[mti][nti][1] + b1;
            v1.x = c[mti][nti][2] + b0; v1.y = c[mti][nti][3] + b1;
            *(float2*)&out[(size_t) r0   *DIM + oc] = v0;
            *(float2*)&out[(size_t)(r0+8)*DIM + oc] = v1;
        }
    }
}

// ---------------- launch ----------------
extern "C" void kernel_launch(void* const* d_in, const int* in_sizes, int n_in,
                              void* d_out, int out_size) {
    const float* x           = (const float*)d_in[0];
    const float* temperature = (const float*)d_in[1];
    const float* Wx          = (const float*)d_in[2];
    const float* bx          = (const float*)d_in[3];
    const float* Wfx         = (const float*)d_in[4];
    const float* bfx         = (const float*)d_in[5];
    const float* Ws          = (const float*)d_in[6];
    const float* bs          = (const float*)d_in[7];
    const float* Wq          = (const float*)d_in[8];
    const float* Wk          = (const float*)d_in[9];
    const float* Wv          = (const float*)d_in[10];
    const float* Wo          = (const float*)d_in[11];
    const float* bo          = (const float*)d_in[12];
    float* out = (float*)d_out;

    cudaFuncSetAttribute(conv_mm_kernel, cudaFuncAttributeMaxDynamicSharedMemorySize, CONV_DSMEM);
    cudaFuncSetAttribute(attn_kernel, cudaFuncAttributeMaxDynamicSharedMemorySize, ATTN_SMEM);
    cudaFuncSetAttribute(outgemm_kernel, cudaFuncAttributeMaxDynamicSharedMemorySize, CONV_DSMEM);

    prep_kernel<<<2048, 256>>>(x, Wx, Wfx, Ws);
    conv_mm_kernel<<<dim3(M_TOT/128, 4, 2), 256, CONV_DSMEM>>>(bx, bfx);
    logits_kernel<<<dim3(NPIX/64, BATCH*HEADS), 256>>>(bs, temperature);
    stoken_mm_kernel<<<dim3(NPIX/512, BATCH*HEADS), 256>>>();
    attn_kernel<<<BATCH*HEADS, 256, ATTN_SMEM>>>(Wq, Wk, Wv);
    pproj_kernel<<<BATCH*HEADS, 256>>>(Wo);
    outgemm_kernel<<<dim3(NPIX/128, BATCH), 256, CONV_DSMEM>>>(bo, out);
}

// round 9
// speedup vs baseline: 1.6038x; 1.0841x over previous
#include <cuda_runtime.h>
#include <math.h>
#include <stdint.h>

#define BATCH  4
#define HEIGHT 128
#define WIDTH  128
#define NPIX   (HEIGHT*WIDTH)      // 16384
#define M_TOT  (BATCH*NPIX)        // 65536
#define DIM    128
#define HEADS  8
#define DH     64
#define INNER  512
#define SLICE  64

// ---------------- scratch (device globals; no allocations) ----------------
__device__ float g_xr  [(size_t)M_TOT*DIM];    // tf32-rounded input [pix][c]
__device__ float g_wb  [18*INNER*DIM];         // conv weights per tap: [pt][o][ci], tf32
__device__ float g_wst [DH*SLICE];             // Ws^T: [c][g]
__device__ float g_xmid [(size_t)M_TOT*INNER]; // conv_x  out (tf32-rounded)
__device__ float g_fxmid[(size_t)M_TOT*INNER]; // conv_fx out (tf32-rounded)
__device__ float g_sw   [(size_t)BATCH*HEADS*NPIX*SLICE];  // tf32-rounded
__device__ float g_snorm[BATCH*HEADS*SLICE];
__device__ float g_stok [BATCH*HEADS*SLICE*DH];
__device__ float g_osl  [BATCH*HEADS*SLICE*DH];
__device__ float g_pt   [BATCH*DIM*INNER];     // P^T: [b][o][h*64+g] (tf32-rounded)

// ---------------- helpers ----------------
__device__ __forceinline__ float tf32r(float f) {
    uint32_t u;
    asm("cvt.rna.tf32.f32 %0, %1;" : "=r"(u) : "f"(f));
    return __uint_as_float(u);
}
__device__ __forceinline__ void cpa16(uint32_t dst, const void* src, int sz) {
    asm volatile("cp.async.cg.shared.global [%0], [%1], 16, %2;" :: "r"(dst), "l"(src), "r"(sz));
}
#define CP_COMMIT() asm volatile("cp.async.commit_group;" ::: "memory")
#define CP_WAIT2()  asm volatile("cp.async.wait_group 2;" ::: "memory")
__device__ __forceinline__ uint32_t smem_u32(const void* p) {
    uint32_t a;
    asm("{ .reg .u64 t; cvta.to.shared.u64 t, %1; cvt.u32.u64 %0, t; }" : "=r"(a) : "l"(p));
    return a;
}
__device__ __forceinline__ void mma_tf32_16x8x8(float* c, const uint32_t* a, const uint32_t* b) {
    asm volatile("mma.sync.aligned.m16n8k8.row.col.f32.tf32.tf32.f32 "
        "{%0,%1,%2,%3}, {%4,%5,%6,%7}, {%8,%9}, {%0,%1,%2,%3};"
        : "+f"(c[0]), "+f"(c[1]), "+f"(c[2]), "+f"(c[3])
        : "r"(a[0]), "r"(a[1]), "r"(a[2]), "r"(a[3]), "r"(b[0]), "r"(b[1]));
}
__device__ __forceinline__ void ldsm_x4(uint32_t* r, uint32_t addr) {
    asm volatile("ldmatrix.sync.aligned.m8n8.x4.shared.b16 {%0,%1,%2,%3}, [%4];"
        : "=r"(r[0]), "=r"(r[1]), "=r"(r[2]), "=r"(r[3]) : "r"(addr));
}

// ---------------- prep ----------------
__global__ void prep_kernel(const float* __restrict__ x,
                            const float* __restrict__ Wx, const float* __restrict__ Wfx,
                            const float* __restrict__ Ws) {
    int stride = gridDim.x * blockDim.x;
    int tid = blockIdx.x * blockDim.x + threadIdx.x;
    for (size_t t = tid; t < (size_t)M_TOT*DIM; t += stride)
        g_xr[t] = tf32r(x[t]);
    for (int t = tid; t < 18*INNER*DIM; t += stride) {
        int ci = t & 127;
        int o  = (t >> 7) & 511;
        int pt = t >> 16;
        int conv = pt / 9, p = pt % 9;
        int ky = p / 3, kx = p % 3;
        const float* W = conv ? Wfx : Wx;
        g_wb[t] = tf32r(W[((o*DIM + ci)*3 + ky)*3 + kx]);
    }
    for (int t = tid; t < DH*SLICE; t += stride) {
        int g = t >> 6, c = t & 63;
        g_wst[c*SLICE + g] = Ws[g*DH + c];
    }
    for (int t = tid; t < BATCH*HEADS*SLICE; t += stride)    g_snorm[t] = 0.f;
    for (int t = tid; t < BATCH*HEADS*SLICE*DH; t += stride) g_stok[t]  = 0.f;
}

// ---------------- tf32 mma conv: kx-shift A reuse + occ 2 ----------------
// loop order: j = ky*12 + c0i*3 + kx ; A stage t = j/3 = ky*4 + c0i (12 stages, ring of 2)
// A tile: 130 pixel rows (gx = -1..128 at smem row gx+1), zero-filled halo.
#define ALD 36
#define A_STAGE (132*ALD)                 // floats per A stage (130 used)
#define B_STAGE (128*ALD)                 // floats per B stage
#define CONV_DSMEM ((2*A_STAGE + 3*B_STAGE)*4)   // 93312 B
#define NCHUNK 36

__device__ __forceinline__ void loadA_stage(int t, float* sA, int tid, int b, int y) {
    int ky = t >> 2;
    int c0 = (t & 3) * 32;
    int yy = y + ky - 1;
    bool rowok = ((unsigned)yy < (unsigned)HEIGHT);
    int yys = rowok ? yy : 0;
    uint32_t sa = smem_u32(sA);
    const float* rowbase = g_xr + ((size_t)(b*HEIGHT + yys)*WIDTH)*DIM + c0;
    #pragma unroll
    for (int r = 0; r < 5; r++) {
        int op = tid + r*256;             // 0..1279, need 0..1039
        if (op < 1040) {
            int row = op >> 3, q = op & 7;    // row 0..129
            int gx = row - 1;
            bool ok = rowok && ((unsigned)gx < (unsigned)WIDTH);
            const float* src = rowbase + (size_t)(ok ? gx : 0)*DIM + q*4;
            cpa16(sa + (row*ALD + q*4)*4, src, ok ? 16 : 0);
        }
    }
}

__device__ __forceinline__ void loadB_chunk(int j, float* sB, int tid, int o0, const float* wt) {
    int ky = j / 12, rem = j % 12;
    int c0 = (rem / 3) * 32;
    int kx = rem % 3;
    int p  = ky*3 + kx;
    uint32_t sb = smem_u32(sB);
    #pragma unroll
    for (int r = 0; r < 4; r++) {
        int op = tid + r*256;
        int row = op >> 3, q = op & 7;
        const float* src = wt + ((size_t)(p*INNER + o0 + row))*DIM + c0 + q*4;
        cpa16(sb + (row*ALD + q*4)*4, src, 16);
    }
}

__global__ __launch_bounds__(256, 2) void conv_mm_kernel(const float* __restrict__ bx,
                                                         const float* __restrict__ bfx) {
    extern __shared__ float smb[];
    float* sA = smb;                      // 2 stages
    float* sB = smb + 2*A_STAGE;          // 3 stages

    int mt = blockIdx.x;
    int b  = mt >> 7, y = mt & 127;
    int m0 = mt * 128;
    int o0 = blockIdx.y * 128;
    int conv = blockIdx.z;
    const float* wt = g_wb + (size_t)conv*9*INNER*DIM;

    int tid  = threadIdx.x;
    int wid  = tid >> 5, lane = tid & 31;
    int g    = lane >> 2, tig = lane & 3;
    int wm   = wid >> 1, wn = wid & 1;

    int lrow = lane & 15;
    int lcol = (lane >> 4) * 4;
    uint32_t bOff = ((wn*64 + lrow)*ALD + lcol) * 4;

    float c[2][8][4];
    #pragma unroll
    for (int i = 0; i < 2; i++)
        #pragma unroll
        for (int j = 0; j < 8; j++)
            #pragma unroll
            for (int q = 0; q < 4; q++) c[i][j][q] = 0.f;

    // prologue: G0 = {A stage 0, B chunk 0}, G1 = {B chunk 1}
    loadA_stage(0, sA, tid, b, y);
    loadB_chunk(0, sB, tid, o0, wt);
    CP_COMMIT();
    loadB_chunk(1, sB + B_STAGE, tid, o0, wt);
    CP_COMMIT();

    for (int it = 0; it < NCHUNK; ++it) {
        int jj = it + 2;
        if (jj < NCHUNK) {
            if (jj % 3 == 0) {
                int t = jj / 3;
                loadA_stage(t, sA + (t & 1)*A_STAGE, tid, b, y);
            }
            loadB_chunk(jj, sB + (jj % 3)*B_STAGE, tid, o0, wt);
        }
        CP_COMMIT();
        CP_WAIT2();
        __syncthreads();

        int kx = it % 3;
        int t  = it / 3;
        uint32_t saU = smem_u32(sA + (t & 1)*A_STAGE)
                     + ((wm*32 + lrow + kx)*ALD + lcol) * 4;
        uint32_t sbU = smem_u32(sB + (it % 3)*B_STAGE) + bOff;
        #pragma unroll
        for (int ks = 0; ks < 4; ks++) {
            uint32_t k8b = ks*8*4;
            uint32_t a[2][4];
            ldsm_x4(a[0], saU + k8b);
            ldsm_x4(a[1], saU + 16*ALD*4 + k8b);
            uint32_t bf[8][2];
            #pragma unroll
            for (int pr = 0; pr < 4; pr++) {
                uint32_t t4[4];
                ldsm_x4(t4, sbU + pr*16*ALD*4 + k8b);
                bf[2*pr  ][0] = t4[0]; bf[2*pr+1][0] = t4[1];
                bf[2*pr  ][1] = t4[2]; bf[2*pr+1][1] = t4[3];
            }
            #pragma unroll
            for (int mti = 0; mti < 2; mti++)
                #pragma unroll
                for (int nti = 0; nti < 8; nti++)
                    mma_tf32_16x8x8(c[mti][nti], a[mti], bf[nti]);
        }
        __syncthreads();
    }

    float* outp = conv ? g_fxmid : g_xmid;
    const float* bias = conv ? bfx : bx;
    #pragma unroll
    for (int mti = 0; mti < 2; mti++) {
        int r0 = m0 + wm*32 + mti*16 + g;
        #pragma unroll
        for (int nti = 0; nti < 8; nti++) {
            int oc = o0 + wn*64 + nti*8 + tig*2;
            float b0 = bias[oc], b1 = bias[oc+1];
            float2 v0, v1;
            v0.x = tf32r(c[mti][nti][0] + b0); v0.y = tf32r(c[mti][nti][1] + b1);
            v1.x = tf32r(c[mti][nti][2] + b0); v1.y = tf32r(c[mti][nti][3] + b1);
            *(float2*)&outp[(size_t) r0   *INNER + oc] = v0;
            *(float2*)&outp[(size_t)(r0+8)*INNER + oc] = v1;
        }
    }
}

// ---------------- logits GEMM + softmax + partial slice_norm (round-3 proven) ----------------
__global__ __launch_bounds__(256) void logits_kernel(const float* __restrict__ bs,
                                                     const float* __restrict__ temp_in) {
    __shared__ __align__(16) float xs[64][68];
    __shared__ __align__(16) float ws[64][68];
    __shared__ float nrm[64];

    int bh = blockIdx.y;
    int b  = bh >> 3, h = bh & 7;
    int n0 = blockIdx.x * 64;
    int tid = threadIdx.x;
    int tx = tid & 15, ty = tid >> 4;

    #pragma unroll
    for (int r = 0; r < 4; r++) {
        int idx = tid + r*256;
        int c = idx >> 4, q = idx & 15;
        *(float4*)&ws[c][4*q] = *(const float4*)&g_wst[c*SLICE + 4*q];
    }
    const float* xbase = g_xmid + ((size_t)(b*NPIX + n0))*INNER + h*DH;
    #pragma unroll
    for (int r = 0; r < 4; r++) {
        int idx = tid + r*256;
        int j = idx >> 4, q = idx & 15;
        *(float4*)&xs[j][4*q] = *(const float4*)&xbase[(size_t)j*INNER + 4*q];
    }
    if (tid < 64) nrm[tid] = 0.f;
    __syncthreads();

    float o_[4][4];
    #pragma unroll
    for (int i = 0; i < 4; i++)
        #pragma unroll
        for (int j = 0; j < 4; j++) o_[i][j] = 0.f;

    #pragma unroll
    for (int k = 0; k < 64; k++) {
        float a0 = xs[ty*4+0][k], a1 = xs[ty*4+1][k];
        float a2 = xs[ty*4+2][k], a3 = xs[ty*4+3][k];
        float4 b4 = *(float4*)&ws[k][tx*4];
        o_[0][0] = fmaf(a0,b4.x,o_[0][0]); o_[0][1] = fmaf(a0,b4.y,o_[0][1]);
        o_[0][2] = fmaf(a0,b4.z,o_[0][2]); o_[0][3] = fmaf(a0,b4.w,o_[0][3]);
        o_[1][0] = fmaf(a1,b4.x,o_[1][0]); o_[1][1] = fmaf(a1,b4.y,o_[1][1]);
        o_[1][2] = fmaf(a1,b4.z,o_[1][2]); o_[1][3] = fmaf(a1,b4.w,o_[1][3]);
        o_[2][0] = fmaf(a2,b4.x,o_[2][0]); o_[2][1] = fmaf(a2,b4.y,o_[2][1]);
        o_[2][2] = fmaf(a2,b4.z,o_[2][2]); o_[2][3] = fmaf(a2,b4.w,o_[2][3]);
        o_[3][0] = fmaf(a3,b4.x,o_[3][0]); o_[3][1] = fmaf(a3,b4.y,o_[3][1]);
        o_[3][2] = fmaf(a3,b4.z,o_[3][2]); o_[3][3] = fmaf(a3,b4.w,o_[3][3]);
    }
    float t = temp_in[h];
    t = fminf(fmaxf(t, 0.1f), 5.0f);
    float invt = 1.f / t;
    __syncthreads();
    #pragma unroll
    for (int i = 0; i < 4; i++)
        #pragma unroll
        for (int j = 0; j < 4; j++)
            xs[ty*4+i][tx*4+j] = (o_[i][j] + bs[tx*4+j]) * invt;
    __syncthreads();

    int wid = tid >> 5, lane = tid & 31;
    float s0 = 0.f, s1 = 0.f;
    for (int r8 = 0; r8 < 8; r8++) {
        int row = wid*8 + r8;
        float v0 = xs[row][lane], v1 = xs[row][lane+32];
        float mx = fmaxf(v0, v1);
        #pragma unroll
        for (int off = 16; off; off >>= 1)
            mx = fmaxf(mx, __shfl_xor_sync(0xffffffffu, mx, off));
        float e0 = __expf(v0 - mx), e1 = __expf(v1 - mx);
        float sm = e0 + e1;
        #pragma unroll
        for (int off = 16; off; off >>= 1)
            sm += __shfl_xor_sync(0xffffffffu, sm, off);
        float inv = 1.f / sm;
        e0 *= inv; e1 *= inv;
        float* swp = g_sw + ((size_t)bh*NPIX + n0 + row)*SLICE;
        swp[lane]      = tf32r(e0);
        swp[lane + 32] = tf32r(e1);
        s0 += e0; s1 += e1;
    }
    atomicAdd(&nrm[lane],     s0);
    atomicAdd(&nrm[lane+32],  s1);
    __syncthreads();
    if (tid < 64) atomicAdd(&g_snorm[bh*SLICE + tid], nrm[tid]);
}

// ---------------- slice_token: tf32 mma, st = SW^T @ FX, 32-way K-split ----------------
__global__ __launch_bounds__(256) void stoken_mm_kernel() {
    __shared__ __align__(16) float Asw[64][68];   // [n][g]
    __shared__ __align__(16) float Bfx[64][68];   // [n][c]
    int bh = blockIdx.y;
    int b  = bh >> 3, h = bh & 7;
    int n0 = blockIdx.x * 512;
    int tid = threadIdx.x;
    int wid = tid >> 5, lane = tid & 31;
    int g = lane >> 2, tig = lane & 3;
    int wm = wid >> 1, wn = wid & 1;

    float c[4][4];
    #pragma unroll
    for (int i = 0; i < 4; i++)
        #pragma unroll
        for (int q = 0; q < 4; q++) c[i][q] = 0.f;

    for (int nn = 0; nn < 512; nn += 64) {
        const float* swb = g_sw    + ((size_t)bh*NPIX + n0 + nn)*SLICE;
        const float* fxb = g_fxmid + ((size_t)(b*NPIX + n0 + nn))*INNER + h*DH;
        #pragma unroll
        for (int r = 0; r < 4; r++) {
            int op = tid + r*256;
            int row = op >> 4, q = op & 15;
            *(float4*)&Asw[row][4*q] = *(const float4*)&swb[(size_t)row*SLICE + 4*q];
            *(float4*)&Bfx[row][4*q] = *(const float4*)&fxb[(size_t)row*INNER + 4*q];
        }
        __syncthreads();
        #pragma unroll
        for (int ks = 0; ks < 8; ks++) {
            int k8 = ks*8;
            uint32_t a[4];
            int r0 = wm*16 + g;
            a[0] = __float_as_uint(Asw[k8 + tig    ][r0]);
            a[1] = __float_as_uint(Asw[k8 + tig    ][r0 + 8]);
            a[2] = __float_as_uint(Asw[k8 + tig + 4][r0]);
            a[3] = __float_as_uint(Asw[k8 + tig + 4][r0 + 8]);
            #pragma unroll
            for (int nti = 0; nti < 4; nti++) {
                uint32_t bf[2];
                int col = wn*32 + nti*8 + g;
                bf[0] = __float_as_uint(Bfx[k8 + tig    ][col]);
                bf[1] = __float_as_uint(Bfx[k8 + tig + 4][col]);
                mma_tf32_16x8x8(c[nti], a, bf);
            }
        }
        __syncthreads();
    }
    int r0 = wm*16 + g;
    #pragma unroll
    for (int nti = 0; nti < 4; nti++) {
        int col = wn*32 + nti*8 + tig*2;
        float* stp = g_stok + bh*4096;
        atomicAdd(&stp[ r0   *64 + col  ], c[nti][0]);
        atomicAdd(&stp[ r0   *64 + col+1], c[nti][1]);
        atomicAdd(&stp[(r0+8)*64 + col  ], c[nti][2]);
        atomicAdd(&stp[(r0+8)*64 + col+1], c[nti][3]);
    }
}

// ---------------- tiny M x M attention per (b,h) ----------------
#define AT_LD 68
#define ATTN_SMEM (5*64*AT_LD*4)
__global__ __launch_bounds__(256) void attn_kernel(const float* __restrict__ Wq,
                                                   const float* __restrict__ Wk,
                                                   const float* __restrict__ Wv) {
    extern __shared__ float smb[];
    float* tok = smb;
    float* wsm = smb + 1*64*AT_LD;
    float* qs  = smb + 2*64*AT_LD;
    float* ks_ = smb + 3*64*AT_LD;
    float* vs  = smb + 4*64*AT_LD;

    int bh  = blockIdx.x;
    int tid = threadIdx.x;

    for (int e = tid; e < 4096; e += 256) {
        int g = e >> 6, c = e & 63;
        float nm = g_snorm[bh*SLICE + g] + 1e-5f;
        tok[g*AT_LD + c] = g_stok[bh*4096 + e] / nm;
    }
    __syncthreads();

    #pragma unroll
    for (int w = 0; w < 3; w++) {
        const float* W = (w == 0) ? Wq : (w == 1) ? Wk : Wv;
        float* dst     = (w == 0) ? qs : (w == 1) ? ks_ : vs;
        for (int e = tid; e < 4096; e += 256)
            wsm[(e >> 6)*AT_LD + (e & 63)] = W[e];
        __syncthreads();
        for (int e = tid; e < 4096; e += 256) {
            int g = e >> 6, d = e & 63;
            float s = 0.f;
            #pragma unroll 8
            for (int c = 0; c < 64; c++)
                s = fmaf(tok[g*AT_LD + c], wsm[d*AT_LD + c], s);
            dst[g*AT_LD + d] = s;
        }
        __syncthreads();
    }
    for (int e = tid; e < 4096; e += 256) {
        int g = e >> 6, j = e & 63;
        float s = 0.f;
        #pragma unroll 8
        for (int d = 0; d < 64; d++)
            s = fmaf(qs[g*AT_LD + d], ks_[j*AT_LD + d], s);
        tok[g*AT_LD + j] = s * 0.125f;
    }
    __syncthreads();
    int wid = tid >> 5, lane = tid & 31;
    for (int r8 = 0; r8 < 8; r8++) {
        int row = wid*8 + r8;
        float v0 = tok[row*AT_LD + lane], v1 = tok[row*AT_LD + lane + 32];
        float mx = fmaxf(v0, v1);
        #pragma unroll
        for (int off = 16; off; off >>= 1)
            mx = fmaxf(mx, __shfl_xor_sync(0xffffffffu, mx, off));
        float e0 = __expf(v0 - mx), e1 = __expf(v1 - mx);
        float sm = e0 + e1;
        #pragma unroll
        for (int off = 16; off; off >>= 1)
            sm += __shfl_xor_sync(0xffffffffu, sm, off);
        float inv = 1.f / sm;
        tok[row*AT_LD + lane]      = e0 * inv;
        tok[row*AT_LD + lane + 32] = e1 * inv;
    }
    __syncthreads();
    for (int e = tid; e < 4096; e += 256) {
        int g = e >> 6, d = e & 63;
        float s = 0.f;
        #pragma unroll 8
        for (int j = 0; j < 64; j++)
            s = fmaf(tok[g*AT_LD + j], vs[j*AT_LD + d], s);
        g_osl[bh*4096 + e] = s;
    }
}

// ---------------- pproj: P^T[b][o][h*64+g] = sum_c osl[bh][g][c] * Wo[o][h*64+c] ----------------
__global__ __launch_bounds__(256) void pproj_kernel(const float* __restrict__ Wo) {
    __shared__ float sosl[64][65];
    __shared__ float swo [128][65];
    int bh = blockIdx.x;
    int b  = bh >> 3, h = bh & 7;
    int tid = threadIdx.x;

    for (int e = tid; e < 4096; e += 256) {
        int g = e >> 6, c = e & 63;
        sosl[g][c] = g_osl[bh*4096 + e];
    }
    for (int e = tid; e < 8192; e += 256) {
        int o = e >> 6, c = e & 63;
        swo[o][c] = Wo[o*INNER + h*DH + c];
    }
    __syncthreads();
    for (int e = tid; e < 8192; e += 256) {
        int o = e >> 6, g = e & 63;
        float s = 0.f;
        #pragma unroll 8
        for (int c = 0; c < 64; c++)
            s = fmaf(sosl[g][c], swo[o][c], s);
        g_pt[(b*DIM + o)*INNER + h*DH + g] = tf32r(s);
    }
}

// ---------------- out GEMM: out_b = SW_b (16384x512) @ P_b^T (512x128), tf32 mma ----------------
#define OG_STAGE (128*ALD)
#define OG_DSMEM (6*OG_STAGE*4)
__global__ __launch_bounds__(256) void outgemm_kernel(const float* __restrict__ bo,
                                                      float* __restrict__ out) {
    extern __shared__ float smb[];
    float* sA = smb;
    float* sB = smb + 3*OG_STAGE;

    int n0 = blockIdx.x * 128;
    int b  = blockIdx.y;
    int tid  = threadIdx.x;
    int wid  = tid >> 5, lane = tid & 31;
    int g    = lane >> 2, tig = lane & 3;
    int wm   = wid >> 1, wn = wid & 1;

    float c[2][8][4];
    #pragma unroll
    for (int i = 0; i < 2; i++)
        #pragma unroll
        for (int j = 0; j < 8; j++)
            #pragma unroll
            for (int q = 0; q < 4; q++) c[i][j][q] = 0.f;

    auto load_chunk = [&](int kk, float* dA, float* dB) {
        int h  = kk >> 1;
        int g0 = (kk & 1) * 32;
        uint32_t sa = smem_u32(dA), sb = smem_u32(dB);
        #pragma unroll
        for (int r = 0; r < 4; r++) {
            int op = tid + r*256;
            int row = op >> 3, q = op & 7;
            const float* srcA = g_sw + ((size_t)((b*HEADS + h)*NPIX) + n0 + row)*SLICE + g0 + q*4;
            cpa16(sa + (row*ALD + q*4)*4, srcA, 16);
            const float* srcB = g_pt + (size_t)(b*DIM + row)*INNER + kk*32 + q*4;
            cpa16(sb + (row*ALD + q*4)*4, srcB, 16);
        }
    };

    load_chunk(0, sA, sB); CP_COMMIT();
    load_chunk(1, sA + OG_STAGE, sB + OG_STAGE); CP_COMMIT();

    for (int it = 0; it < 16; ++it) {
        int j = it + 2;
        if (j < 16) {
            int s2 = j % 3;
            load_chunk(j, sA + s2*OG_STAGE, sB + s2*OG_STAGE);
        }
        CP_COMMIT();
        CP_WAIT2();
        __syncthreads();

        const float* As = sA + (it % 3)*OG_STAGE;
        const float* Bs = sB + (it % 3)*OG_STAGE;
        #pragma unroll
        for (int ks = 0; ks < 4; ks++) {
            int k8 = ks*8;
            uint32_t a[2][4];
            #pragma unroll
            for (int mti = 0; mti < 2; mti++) {
                int r0 = wm*32 + mti*16 + g;
                a[mti][0] = __float_as_uint(As[ r0    *ALD + k8 + tig]);
                a[mti][1] = __float_as_uint(As[(r0+8) *ALD + k8 + tig]);
                a[mti][2] = __float_as_uint(As[ r0    *ALD + k8 + tig + 4]);
                a[mti][3] = __float_as_uint(As[(r0+8) *ALD + k8 + tig + 4]);
            }
            uint32_t bf[8][2];
            #pragma unroll
            for (int nti = 0; nti < 8; nti++) {
                int n = wn*64 + nti*8 + g;
                bf[nti][0] = __float_as_uint(Bs[n*ALD + k8 + tig]);
                bf[nti][1] = __float_as_uint(Bs[n*ALD + k8 + tig + 4]);
            }
            #pragma unroll
            for (int mti = 0; mti < 2; mti++)
                #pragma unroll
                for (int nti = 0; nti < 8; nti++)
                    mma_tf32_16x8x8(c[mti][nti], a[mti], bf[nti]);
        }
        __syncthreads();
    }

    #pragma unroll
    for (int mti = 0; mti < 2; mti++) {
        int r0 = b*NPIX + n0 + wm*32 + mti*16 + g;
        #pragma unroll
        for (int nti = 0; nti < 8; nti++) {
            int oc = wn*64 + nti*8 + tig*2;
            float b0 = bo[oc], b1 = bo[oc+1];
            float2 v0, v1;
            v0.x = c[mti][nti][0] + b0; v0.y = c[mti][nti][1] + b1;
            v1.x = c[mti][nti][2] + b0; v1.y = c[mti][nti][3] + b1;
            *(float2*)&out[(size_t) r0   *DIM + oc] = v0;
            *(float2*)&out[(size_t)(r0+8)*DIM + oc] = v1;
        }
    }
}

// ---------------- launch ----------------
extern "C" void kernel_launch(void* const* d_in, const int* in_sizes, int n_in,
                              void* d_out, int out_size) {
    const float* x           = (const float*)d_in[0];
    const float* temperature = (const float*)d_in[1];
    const float* Wx          = (const float*)d_in[2];
    const float* bx          = (const float*)d_in[3];
    const float* Wfx         = (const float*)d_in[4];
    const float* bfx         = (const float*)d_in[5];
    const float* Ws          = (const float*)d_in[6];
    const float* bs          = (const float*)d_in[7];
    const float* Wq          = (const float*)d_in[8];
    const float* Wk          = (const float*)d_in[9];
    const float* Wv          = (const float*)d_in[10];
    const float* Wo          = (const float*)d_in[11];
    const float* bo          = (const float*)d_in[12];
    float* out = (float*)d_out;

    cudaFuncSetAttribute(conv_mm_kernel, cudaFuncAttributeMaxDynamicSharedMemorySize, CONV_DSMEM);
    cudaFuncSetAttribute(attn_kernel, cudaFuncAttributeMaxDynamicSharedMemorySize, ATTN_SMEM);
    cudaFuncSetAttribute(outgemm_kernel, cudaFuncAttributeMaxDynamicSharedMemorySize, OG_DSMEM);

    prep_kernel<<<2048, 256>>>(x, Wx, Wfx, Ws);
    conv_mm_kernel<<<dim3(M_TOT/128, 4, 2), 256, CONV_DSMEM>>>(bx, bfx);
    logits_kernel<<<dim3(NPIX/64, BATCH*HEADS), 256>>>(bs, temperature);
    stoken_mm_kernel<<<dim3(NPIX/512, BATCH*HEADS), 256>>>();
    attn_kernel<<<BATCH*HEADS, 256, ATTN_SMEM>>>(Wq, Wk, Wv);
    pproj_kernel<<<BATCH*HEADS, 256>>>(Wo);
    outgemm_kernel<<<dim3(NPIX/128, BATCH), 256, OG_DSMEM>>>(bo, out);
}